// round 5
// baseline (speedup 1.0000x reference)
#include <cuda_runtime.h>

// Swin window attention, 4-kernel split:
//  K0: fuse rel-pos bias + shift mask into g_bm[64][4][49][49]
//  K1: qkv GEMM  (M=200704, N=384, K=128) + bias, q pre-scaled -> g_qkv
//  K2: per-(window, head-pair) attention -> g_ctx
//  K3: proj GEMM (M=200704, N=128, K=128) + bias -> out
// All GEMMs: mma.sync.m16n8k8 tf32, fragments via ldmatrix.

constexpr int NTOK = 49;
constexpr int NHD  = 4;
constexpr float SCALE = 0.17677669529663687f; // 32^-0.5
constexpr long long TOK = 200704ll;           // 4096 * 49

__device__ float g_qkv[TOK * 384];            // qkv activations (f32)
__device__ float g_ctx[TOK * 128];            // attention context (f32)
__device__ float g_bm[64 * 4 * 49 * 49];      // fused bias+mask

// ---------------- helpers ----------------
__device__ __forceinline__ unsigned f2tf(float x) {
    unsigned r;
    asm("cvt.rna.tf32.f32 %0, %1;" : "=r"(r) : "f"(x));
    return r;
}
__device__ __forceinline__ float4 f2tf4(float4 v) {
    float4 t;
    t.x = __uint_as_float(f2tf(v.x));
    t.y = __uint_as_float(f2tf(v.y));
    t.z = __uint_as_float(f2tf(v.z));
    t.w = __uint_as_float(f2tf(v.w));
    return t;
}
__device__ __forceinline__ void mma8(float c[4],
                                     unsigned a0, unsigned a1, unsigned a2, unsigned a3,
                                     unsigned b0, unsigned b1) {
    asm volatile(
        "mma.sync.aligned.m16n8k8.row.col.f32.tf32.tf32.f32 "
        "{%0,%1,%2,%3},{%4,%5,%6,%7},{%8,%9},{%0,%1,%2,%3};"
        : "+f"(c[0]), "+f"(c[1]), "+f"(c[2]), "+f"(c[3])
        : "r"(a0), "r"(a1), "r"(a2), "r"(a3), "r"(b0), "r"(b1));
}
__device__ __forceinline__ unsigned sptr(const float* p) {
    return (unsigned)__cvta_generic_to_shared(p);
}
__device__ __forceinline__ void ldA(unsigned r[4], const float* base, int L) {
    int lane = threadIdx.x & 31;
    const float* p = base + ((lane & 7) + ((lane & 8) ? 8 : 0)) * L + ((lane & 16) ? 4 : 0);
    unsigned a = sptr(p);
    asm volatile("ldmatrix.sync.aligned.m8n8.x4.shared.b16 {%0,%1,%2,%3}, [%4];"
                 : "=r"(r[0]), "=r"(r[1]), "=r"(r[2]), "=r"(r[3]) : "r"(a));
}
__device__ __forceinline__ void ldB(unsigned r[2], const float* base, int L) {
    int lane = threadIdx.x & 31;
    const float* p = base + (lane & 7) * L + ((lane & 8) ? 4 : 0);
    unsigned a = sptr(p);
    asm volatile("ldmatrix.sync.aligned.m8n8.x2.shared.b16 {%0,%1}, [%2];"
                 : "=r"(r[0]), "=r"(r[1]) : "r"(a));
}
__device__ __forceinline__ unsigned ldsm(const float* p) { return __float_as_uint(*p); }

// ---------------- K0: fused bias+mask table ----------------
__global__ void biasfuse_kernel(const float* __restrict__ tbl,
                                const int*   __restrict__ idx,
                                const float* __restrict__ mask) {
    long i = (long)blockIdx.x * 256 + threadIdx.x;   // 64*4*49*49 = 614656 exactly
    int m = (int)(i % 49);
    long r = i / 49;
    int n = (int)(r % 49); r /= 49;
    int h = (int)(r % 4);
    int wn = (int)(r / 4);
    g_bm[i] = __ldg(tbl + __ldg(idx + n * 49 + m) * NHD + h)
            + __ldg(mask + wn * 2401 + n * 49 + m);
}

// ---------------- K1/K3: GEMM  C[M,N] = A[M,128] @ W[N,128]^T + bias ----------------
constexpr int GA = 0;                 // A tile 128 x 132
constexpr int GB = 128 * 132;         // B tile  64 x 132
constexpr int GEMM_SMEM = (128 * 132 + 64 * 132) * 4;   // 101376 B

__global__ __launch_bounds__(256, 2)
void gemm_tf32_kernel(const float* __restrict__ A,
                      const float* __restrict__ W,
                      const float* __restrict__ bias,
                      float* __restrict__ C,
                      int ldc, int qscale) {
    extern __shared__ float sm[];
    const int tid = threadIdx.x, lane = tid & 31, w = tid >> 5;
    const int wm = w & 3, wn = w >> 2;
    const int ar = lane >> 2, ac = lane & 3;
    const long mt = blockIdx.x, nt = blockIdx.y;

    const float4* ag = (const float4*)(A + mt * 128 * 128);
    for (int i = tid; i < 128 * 32; i += 256) {
        int r = i >> 5, c4 = i & 31;
        *(float4*)(sm + GA + r * 132 + c4 * 4) = f2tf4(__ldg(ag + i));
    }
    const float4* wg = (const float4*)(W + nt * 64 * 128);
    for (int i = tid; i < 64 * 32; i += 256) {
        int r = i >> 5, c4 = i & 31;
        *(float4*)(sm + GB + r * 132 + c4 * 4) = f2tf4(__ldg(wg + i));
    }
    __syncthreads();

    float acc[2][4][4];
    #pragma unroll
    for (int hf = 0; hf < 2; ++hf)
        #pragma unroll
        for (int t = 0; t < 4; ++t)
            #pragma unroll
            for (int j = 0; j < 4; ++j) acc[hf][t][j] = 0.f;

    #pragma unroll 4
    for (int k0 = 0; k0 < 128; k0 += 8) {
        unsigned a0[4], a1[4];
        ldA(a0, sm + GA + (wm * 32) * 132 + k0, 132);
        ldA(a1, sm + GA + (wm * 32 + 16) * 132 + k0, 132);
        #pragma unroll
        for (int t = 0; t < 4; ++t) {
            unsigned bb[2];
            ldB(bb, sm + GB + (wn * 32 + t * 8) * 132 + k0, 132);
            mma8(acc[0][t], a0[0], a0[1], a0[2], a0[3], bb[0], bb[1]);
            mma8(acc[1][t], a1[0], a1[1], a1[2], a1[3], bb[0], bb[1]);
        }
    }

    #pragma unroll
    for (int hf = 0; hf < 2; ++hf)
        #pragma unroll
        for (int t = 0; t < 4; ++t) {
            int col = (int)nt * 64 + wn * 32 + t * 8 + 2 * ac;
            float sc = (qscale && col < 128) ? SCALE : 1.f;
            float b0v = __ldg(bias + col);
            float b1v = __ldg(bias + col + 1);
            long row = mt * 128 + wm * 32 + hf * 16 + ar;
            C[row * ldc + col]            = (acc[hf][t][0] + b0v) * sc;
            C[row * ldc + col + 1]        = (acc[hf][t][1] + b1v) * sc;
            C[(row + 8) * ldc + col]      = (acc[hf][t][2] + b0v) * sc;
            C[(row + 8) * ldc + col + 1]  = (acc[hf][t][3] + b1v) * sc;
        }
}

// ---------------- K2: attention per (window, head-pair) ----------------
constexpr int QS2 = 0;                 // 64 x 68 (two heads side-by-side in 64 cols)
constexpr int KS2 = QS2 + 64 * 68;
constexpr int VS2 = KS2 + 64 * 68;
constexpr int SS2 = VS2 + 64 * 68;     // 2 x (64 x 68) score buffers
constexpr int ATTN_SMEM = (SS2 + 2 * 64 * 68) * 4;   // 87040 B

__global__ __launch_bounds__(256, 2)
void attn_kernel(float* __restrict__ unused) {
    extern __shared__ float sm[];
    const int tid = threadIdx.x, lane = tid & 31, w = tid >> 5;
    const int wm = w & 3, hh = w >> 2;
    const int ar = lane >> 2, ac = lane & 3;
    const int win = blockIdx.x, hp = blockIdx.y;
    const int h = hp * 2 + hh;
    const long tok0 = (long)win * NTOK;

    // zero q/k/v pad rows
    for (int i = tid; i < SS2; i += 256) sm[i] = 0.f;
    __syncthreads();

    // stage q,k,v (49 rows x 64 cols each) as tf32, stride 68
    {
        const float* qb = g_qkv + tok0 * 384 + hp * 64;
        const float* kb = qb + 128;
        const float* vb = qb + 256;
        for (int i = tid; i < NTOK * 16; i += 256) {
            int r = i >> 4, c4 = (i & 15) * 4;
            long off = (long)r * 384 + c4;
            *(float4*)(sm + QS2 + r * 68 + c4) = f2tf4(__ldg((const float4*)(qb + off)));
            *(float4*)(sm + KS2 + r * 68 + c4) = f2tf4(__ldg((const float4*)(kb + off)));
            *(float4*)(sm + VS2 + r * 68 + c4) = f2tf4(__ldg((const float4*)(vb + off)));
        }
    }
    __syncthreads();

    float* sb = sm + SS2 + hh * (64 * 68);

    // scores S = Q_h @ K_h^T (64x64, K=32); warp tile 16x64
    {
        float sacc[8][4];
        #pragma unroll
        for (int t = 0; t < 8; ++t)
            #pragma unroll
            for (int j = 0; j < 4; ++j) sacc[t][j] = 0.f;

        #pragma unroll
        for (int kk = 0; kk < 4; ++kk) {
            int k0 = hh * 32 + kk * 8;
            unsigned a[4];
            ldA(a, sm + QS2 + (wm * 16) * 68 + k0, 68);
            #pragma unroll
            for (int t = 0; t < 8; ++t) {
                unsigned bb[2];
                ldB(bb, sm + KS2 + (t * 8) * 68 + k0, 68);
                mma8(sacc[t], a[0], a[1], a[2], a[3], bb[0], bb[1]);
            }
        }
        #pragma unroll
        for (int t = 0; t < 8; ++t) {
            int m0 = t * 8 + 2 * ac;
            int r0 = wm * 16 + ar;
            sb[r0 * 68 + m0]           = sacc[t][0];
            sb[r0 * 68 + m0 + 1]       = sacc[t][1];
            sb[(r0 + 8) * 68 + m0]     = sacc[t][2];
            sb[(r0 + 8) * 68 + m0 + 1] = sacc[t][3];
        }
    }
    __syncthreads();

    // softmax with fused bias+mask (mask-window = win & 63)
    {
        const float* bmh = g_bm + ((long)((win & 63) * 4 + h) * 49) * 49;
        #pragma unroll 4
        for (int rr = 0; rr < 16; ++rr) {
            int n = wm * 16 + rr;
            float s0 = -1e30f, s1 = -1e30f;
            if (n < NTOK) {
                if (lane < NTOK)
                    s0 = sb[n * 68 + lane] + __ldg(bmh + n * 49 + lane);
                int m1 = lane + 32;
                if (m1 < NTOK)
                    s1 = sb[n * 68 + m1] + __ldg(bmh + n * 49 + m1);
            }
            float mx = fmaxf(s0, s1);
            #pragma unroll
            for (int o = 16; o; o >>= 1) mx = fmaxf(mx, __shfl_xor_sync(0xffffffffu, mx, o));
            float e0 = (s0 > -1e29f) ? __expf(s0 - mx) : 0.f;
            float e1 = (s1 > -1e29f) ? __expf(s1 - mx) : 0.f;
            float sum = e0 + e1;
            #pragma unroll
            for (int o = 16; o; o >>= 1) sum += __shfl_xor_sync(0xffffffffu, sum, o);
            if (n < NTOK) {
                float inv = 1.f / sum;
                sb[n * 68 + lane]      = __uint_as_float(f2tf(e0 * inv));
                sb[n * 68 + lane + 32] = __uint_as_float(f2tf(e1 * inv));
            } else {
                sb[n * 68 + lane]      = 0.f;
                sb[n * 68 + lane + 32] = 0.f;
            }
        }
    }
    __syncthreads();

    // ctx = P @ V_h (64x32, K=64); warp tile 16x32
    {
        float cacc[4][4];
        #pragma unroll
        for (int u = 0; u < 4; ++u)
            #pragma unroll
            for (int j = 0; j < 4; ++j) cacc[u][j] = 0.f;

        #pragma unroll
        for (int k0 = 0; k0 < 64; k0 += 8) {
            unsigned a[4];
            ldA(a, sb + (wm * 16) * 68 + k0, 68);
            #pragma unroll
            for (int u = 0; u < 4; ++u) {
                int n0 = hh * 32 + u * 8;
                unsigned b0 = ldsm(sm + VS2 + (k0 + ac) * 68 + n0 + ar);
                unsigned b1 = ldsm(sm + VS2 + (k0 + 4 + ac) * 68 + n0 + ar);
                mma8(cacc[u], a[0], a[1], a[2], a[3], b0, b1);
            }
        }
        #pragma unroll
        for (int u = 0; u < 4; ++u) {
            int col = h * 32 + u * 8 + 2 * ac;
            int r0 = wm * 16 + ar;
            if (r0 < NTOK) {
                g_ctx[(tok0 + r0) * 128 + col]     = cacc[u][0];
                g_ctx[(tok0 + r0) * 128 + col + 1] = cacc[u][1];
            }
            if (r0 + 8 < NTOK) {
                g_ctx[(tok0 + r0 + 8) * 128 + col]     = cacc[u][2];
                g_ctx[(tok0 + r0 + 8) * 128 + col + 1] = cacc[u][3];
            }
        }
    }
}

// ---------------- launch ----------------
extern "C" void kernel_launch(void* const* d_in, const int* in_sizes, int n_in,
                              void* d_out, int out_size) {
    const float* x      = (const float*)d_in[0];
    const float* mask   = (const float*)d_in[1];
    const float* qkv_w  = (const float*)d_in[2];
    const float* qkv_b  = (const float*)d_in[3];
    const float* proj_w = (const float*)d_in[4];
    const float* proj_b = (const float*)d_in[5];
    const float* tbl    = (const float*)d_in[6];
    const int*   idx    = (const int*)d_in[7];

    cudaFuncSetAttribute(gemm_tf32_kernel,
                         cudaFuncAttributeMaxDynamicSharedMemorySize, GEMM_SMEM);
    cudaFuncSetAttribute(attn_kernel,
                         cudaFuncAttributeMaxDynamicSharedMemorySize, ATTN_SMEM);

    float* qkv_s; cudaGetSymbolAddress((void**)&qkv_s, g_qkv);
    float* ctx_s; cudaGetSymbolAddress((void**)&ctx_s, g_ctx);

    // K0: fused bias+mask
    biasfuse_kernel<<<2401, 256>>>(tbl, idx, mask);

    // K1: qkv GEMM (M=200704, N=384)
    {
        dim3 grid(1568, 6);
        gemm_tf32_kernel<<<grid, 256, GEMM_SMEM>>>(x, qkv_w, qkv_b, qkv_s, 384, 1);
    }

    // K2: attention
    {
        dim3 grid(4096, 2);
        attn_kernel<<<grid, 256, ATTN_SMEM>>>(nullptr);
    }

    // K3: proj GEMM (M=200704, N=128)
    {
        dim3 grid(1568, 2);
        gemm_tf32_kernel<<<grid, 256, GEMM_SMEM>>>(ctx_s, proj_w, proj_b,
                                                   (float*)d_out, 128, 0);
    }
}

// round 7
// speedup vs baseline: 1.5301x; 1.5301x over previous
#include <cuda_runtime.h>

// Swin window attention, 4-kernel split:
//  K0: fuse rel-pos bias + shift mask into g_bm[64][4][49][49]
//  K1: qkv GEMM  (M=200704, N=384, K=128) + bias, q pre-scaled -> g_qkv
//      A-resident / B-streamed with register prefetch pipeline
//  K2: per-(window, head-pair) attention -> g_ctx
//  K3: proj GEMM (M=200704, N=128, K=128) + bias -> out (same GEMM kernel)
// All GEMMs: mma.sync.m16n8k8 tf32, fragments via ldmatrix.

constexpr int NTOK = 49;
constexpr int NHD  = 4;
constexpr float SCALE = 0.17677669529663687f; // 32^-0.5
constexpr long long TOK = 200704ll;           // 4096 * 49

__device__ float g_qkv[TOK * 384];            // qkv activations (f32)
__device__ float g_ctx[TOK * 128];            // attention context (f32)
__device__ float g_bm[64 * 4 * 49 * 49 + 64]; // fused bias+mask (padded)

// ---------------- helpers ----------------
__device__ __forceinline__ unsigned f2tf(float x) {
    unsigned r;
    asm("cvt.rna.tf32.f32 %0, %1;" : "=r"(r) : "f"(x));
    return r;
}
__device__ __forceinline__ float4 f2tf4(float4 v) {
    float4 t;
    t.x = __uint_as_float(f2tf(v.x));
    t.y = __uint_as_float(f2tf(v.y));
    t.z = __uint_as_float(f2tf(v.z));
    t.w = __uint_as_float(f2tf(v.w));
    return t;
}
__device__ __forceinline__ void mma8(float c[4],
                                     unsigned a0, unsigned a1, unsigned a2, unsigned a3,
                                     unsigned b0, unsigned b1) {
    asm volatile(
        "mma.sync.aligned.m16n8k8.row.col.f32.tf32.tf32.f32 "
        "{%0,%1,%2,%3},{%4,%5,%6,%7},{%8,%9},{%0,%1,%2,%3};"
        : "+f"(c[0]), "+f"(c[1]), "+f"(c[2]), "+f"(c[3])
        : "r"(a0), "r"(a1), "r"(a2), "r"(a3), "r"(b0), "r"(b1));
}
__device__ __forceinline__ unsigned sptr(const float* p) {
    return (unsigned)__cvta_generic_to_shared(p);
}
__device__ __forceinline__ void ldA(unsigned r[4], const float* base, int L) {
    int lane = threadIdx.x & 31;
    const float* p = base + ((lane & 7) + ((lane & 8) ? 8 : 0)) * L + ((lane & 16) ? 4 : 0);
    unsigned a = sptr(p);
    asm volatile("ldmatrix.sync.aligned.m8n8.x4.shared.b16 {%0,%1,%2,%3}, [%4];"
                 : "=r"(r[0]), "=r"(r[1]), "=r"(r[2]), "=r"(r[3]) : "r"(a));
}
__device__ __forceinline__ void ldB(unsigned r[2], const float* base, int L) {
    int lane = threadIdx.x & 31;
    const float* p = base + (lane & 7) * L + ((lane & 8) ? 4 : 0);
    unsigned a = sptr(p);
    asm volatile("ldmatrix.sync.aligned.m8n8.x2.shared.b16 {%0,%1}, [%2];"
                 : "=r"(r[0]), "=r"(r[1]) : "r"(a));
}
__device__ __forceinline__ unsigned ldsm(const float* p) { return __float_as_uint(*p); }

// ---------------- K0: fused bias+mask table ----------------
__global__ void biasfuse_kernel(const float* __restrict__ tbl,
                                const int*   __restrict__ idx,
                                const float* __restrict__ mask) {
    long i = (long)blockIdx.x * 256 + threadIdx.x;   // 64*4*49*49 = 614656 exactly
    int m = (int)(i % 49);
    long r = i / 49;
    int n = (int)(r % 49); r /= 49;
    int h = (int)(r % 4);
    int wn = (int)(r / 4);
    g_bm[i] = __ldg(tbl + __ldg(idx + n * 49 + m) * NHD + h)
            + __ldg(mask + wn * 2401 + n * 49 + m);
}

// ---------------- K1/K3: GEMM  C[M,N] = A[M,128] @ W[N,128]^T + bias ----------------
// A tile (128x128) resident; W streamed in 64-col chunks with register prefetch.
constexpr int GA = 0;                 // A tile 128 x 132
constexpr int GB = 128 * 132;         // B chunk 64 x 132
constexpr int GEMM_SMEM = (128 * 132 + 64 * 132) * 4;   // 101376 B

__global__ __launch_bounds__(256, 2)
void gemm_tf32_kernel(const float* __restrict__ A,
                      const float* __restrict__ W,
                      const float* __restrict__ bias,
                      float* __restrict__ C,
                      int ldc, int n_chunks, int qscale) {
    extern __shared__ float sm[];
    const int tid = threadIdx.x, lane = tid & 31, w = tid >> 5;
    const int wm = w & 3, wn = w >> 2;
    const int ar = lane >> 2, ac = lane & 3;
    const long mt = blockIdx.x;

    // stage A (128x128 = 4096 float4 -> tf32, STS.128), once
    {
        const float4* ag = (const float4*)(A + mt * 128 * 128);
        #pragma unroll
        for (int i = 0; i < 16; ++i) {
            int j = tid + i * 256;
            int r = j >> 5, c4 = j & 31;
            *(float4*)(sm + GA + r * 132 + c4 * 4) = f2tf4(__ldg(ag + j));
        }
    }
    // stage B chunk 0 (64x128 = 2048 float4)
    {
        const float4* wg = (const float4*)W;
        #pragma unroll
        for (int i = 0; i < 8; ++i) {
            int j = tid + i * 256;
            int r = j >> 5, c4 = j & 31;
            *(float4*)(sm + GB + r * 132 + c4 * 4) = f2tf4(__ldg(wg + j));
        }
    }
    __syncthreads();

    for (int nt = 0; nt < n_chunks; ++nt) {
        // prefetch next B chunk into registers (overlaps with compute below)
        float4 breg[8];
        const bool pf = (nt + 1 < n_chunks);
        if (pf) {
            const float4* wg = (const float4*)(W + (long)(nt + 1) * 64 * 128);
            #pragma unroll
            for (int i = 0; i < 8; ++i) breg[i] = __ldg(wg + tid + i * 256);
        }

        // compute 128x64 tile
        float acc[2][4][4];
        #pragma unroll
        for (int hf = 0; hf < 2; ++hf)
            #pragma unroll
            for (int t = 0; t < 4; ++t)
                #pragma unroll
                for (int j = 0; j < 4; ++j) acc[hf][t][j] = 0.f;

        #pragma unroll 4
        for (int k0 = 0; k0 < 128; k0 += 8) {
            unsigned a0[4], a1[4];
            ldA(a0, sm + GA + (wm * 32) * 132 + k0, 132);
            ldA(a1, sm + GA + (wm * 32 + 16) * 132 + k0, 132);
            #pragma unroll
            for (int t = 0; t < 4; ++t) {
                unsigned bb[2];
                ldB(bb, sm + GB + (wn * 32 + t * 8) * 132 + k0, 132);
                mma8(acc[0][t], a0[0], a0[1], a0[2], a0[3], bb[0], bb[1]);
                mma8(acc[1][t], a1[0], a1[1], a1[2], a1[3], bb[0], bb[1]);
            }
        }

        // epilogue: bias (+ q scale) and store
        #pragma unroll
        for (int hf = 0; hf < 2; ++hf)
            #pragma unroll
            for (int t = 0; t < 4; ++t) {
                int col = nt * 64 + wn * 32 + t * 8 + 2 * ac;
                float sc = (qscale && col < 128) ? SCALE : 1.f;
                float b0v = __ldg(bias + col);
                float b1v = __ldg(bias + col + 1);
                long row = mt * 128 + wm * 32 + hf * 16 + ar;
                C[row * ldc + col]            = (acc[hf][t][0] + b0v) * sc;
                C[row * ldc + col + 1]        = (acc[hf][t][1] + b1v) * sc;
                C[(row + 8) * ldc + col]      = (acc[hf][t][2] + b0v) * sc;
                C[(row + 8) * ldc + col + 1]  = (acc[hf][t][3] + b1v) * sc;
            }

        if (pf) {
            __syncthreads();   // all warps done reading current B
            #pragma unroll
            for (int i = 0; i < 8; ++i) {
                int j = tid + i * 256;
                int r = j >> 5, c4 = j & 31;
                *(float4*)(sm + GB + r * 132 + c4 * 4) = f2tf4(breg[i]);
            }
            __syncthreads();   // new B visible
        }
    }
}

// ---------------- K2: attention per (window, head-pair) ----------------
constexpr int QS2 = 0;                 // 64 x 68 (two heads side-by-side in 64 cols)
constexpr int KS2 = QS2 + 64 * 68;
constexpr int VS2 = KS2 + 64 * 68;
constexpr int SS2 = VS2 + 64 * 68;     // 2 x (64 x 68) score buffers
constexpr int ATTN_SMEM = (SS2 + 2 * 64 * 68) * 4;   // 87040 B

__global__ __launch_bounds__(256, 2)
void attn_kernel() {
    extern __shared__ float sm[];
    const int tid = threadIdx.x, lane = tid & 31, w = tid >> 5;
    const int wm = w & 3, hh = w >> 2;
    const int ar = lane >> 2, ac = lane & 3;
    const int win = blockIdx.x, hp = blockIdx.y;
    const int h = hp * 2 + hh;
    const long tok0 = (long)win * NTOK;

    // zero only pad rows (49..63) x 64 cols of q,k,v
    {
        const float4 z = make_float4(0.f, 0.f, 0.f, 0.f);
        for (int i = tid; i < 15 * 16 * 3; i += 256) {
            int buf = i / (15 * 16);
            int rem = i - buf * 15 * 16;
            int r = 49 + (rem >> 4), c4 = rem & 15;
            *(float4*)(sm + buf * (64 * 68) + r * 68 + c4 * 4) = z;
        }
    }
    // stage q,k,v (49 rows x 64 cols each) as tf32, stride 68
    {
        const float* qb = g_qkv + tok0 * 384 + hp * 64;
        const float* kb = qb + 128;
        const float* vb = qb + 256;
        for (int i = tid; i < NTOK * 16; i += 256) {
            int r = i >> 4, c4 = (i & 15) * 4;
            long off = (long)r * 384 + c4;
            *(float4*)(sm + QS2 + r * 68 + c4) = f2tf4(__ldg((const float4*)(qb + off)));
            *(float4*)(sm + KS2 + r * 68 + c4) = f2tf4(__ldg((const float4*)(kb + off)));
            *(float4*)(sm + VS2 + r * 68 + c4) = f2tf4(__ldg((const float4*)(vb + off)));
        }
    }
    __syncthreads();

    float* sb = sm + SS2 + hh * (64 * 68);

    // scores S = Q_h @ K_h^T (64x64, K=32); warp tile 16x64
    {
        float sacc[8][4];
        #pragma unroll
        for (int t = 0; t < 8; ++t)
            #pragma unroll
            for (int j = 0; j < 4; ++j) sacc[t][j] = 0.f;

        #pragma unroll
        for (int kk = 0; kk < 4; ++kk) {
            int k0 = hh * 32 + kk * 8;
            unsigned a[4];
            ldA(a, sm + QS2 + (wm * 16) * 68 + k0, 68);
            #pragma unroll
            for (int t = 0; t < 8; ++t) {
                unsigned bb[2];
                ldB(bb, sm + KS2 + (t * 8) * 68 + k0, 68);
                mma8(sacc[t], a[0], a[1], a[2], a[3], bb[0], bb[1]);
            }
        }
        #pragma unroll
        for (int t = 0; t < 8; ++t) {
            int m0 = t * 8 + 2 * ac;
            int r0 = wm * 16 + ar;
            sb[r0 * 68 + m0]           = sacc[t][0];
            sb[r0 * 68 + m0 + 1]       = sacc[t][1];
            sb[(r0 + 8) * 68 + m0]     = sacc[t][2];
            sb[(r0 + 8) * 68 + m0 + 1] = sacc[t][3];
        }
    }
    __syncthreads();

    // softmax with fused bias+mask (mask-window = win & 63)
    {
        const float* bmh = g_bm + ((long)((win & 63) * 4 + h) * 49) * 49;
        #pragma unroll 4
        for (int rr = 0; rr < 16; ++rr) {
            int n = wm * 16 + rr;
            float s0 = -1e30f, s1 = -1e30f;
            if (n < NTOK) {
                if (lane < NTOK)
                    s0 = sb[n * 68 + lane] + __ldg(bmh + n * 49 + lane);
                int m1 = lane + 32;
                if (m1 < NTOK)
                    s1 = sb[n * 68 + m1] + __ldg(bmh + n * 49 + m1);
            }
            float mx = fmaxf(s0, s1);
            #pragma unroll
            for (int o = 16; o; o >>= 1) mx = fmaxf(mx, __shfl_xor_sync(0xffffffffu, mx, o));
            float e0 = (s0 > -1e29f) ? __expf(s0 - mx) : 0.f;
            float e1 = (s1 > -1e29f) ? __expf(s1 - mx) : 0.f;
            float sum = e0 + e1;
            #pragma unroll
            for (int o = 16; o; o >>= 1) sum += __shfl_xor_sync(0xffffffffu, sum, o);
            if (n < NTOK) {
                float inv = __fdividef(1.f, sum);
                sb[n * 68 + lane]      = __uint_as_float(f2tf(e0 * inv));
                sb[n * 68 + lane + 32] = __uint_as_float(f2tf(e1 * inv));
            } else {
                sb[n * 68 + lane]      = 0.f;
                sb[n * 68 + lane + 32] = 0.f;
            }
        }
    }
    __syncthreads();

    // ctx = P @ V_h (64x32, K=64); warp tile 16x32
    {
        float cacc[4][4];
        #pragma unroll
        for (int u = 0; u < 4; ++u)
            #pragma unroll
            for (int j = 0; j < 4; ++j) cacc[u][j] = 0.f;

        #pragma unroll
        for (int k0 = 0; k0 < 64; k0 += 8) {
            unsigned a[4];
            ldA(a, sb + (wm * 16) * 68 + k0, 68);
            #pragma unroll
            for (int u = 0; u < 4; ++u) {
                int n0 = hh * 32 + u * 8;
                unsigned b0 = ldsm(sm + VS2 + (k0 + ac) * 68 + n0 + ar);
                unsigned b1 = ldsm(sm + VS2 + (k0 + 4 + ac) * 68 + n0 + ar);
                mma8(cacc[u], a[0], a[1], a[2], a[3], b0, b1);
            }
        }
        #pragma unroll
        for (int u = 0; u < 4; ++u) {
            int col = h * 32 + u * 8 + 2 * ac;
            int r0 = wm * 16 + ar;
            if (r0 < NTOK) {
                g_ctx[(tok0 + r0) * 128 + col]     = cacc[u][0];
                g_ctx[(tok0 + r0) * 128 + col + 1] = cacc[u][1];
            }
            if (r0 + 8 < NTOK) {
                g_ctx[(tok0 + r0 + 8) * 128 + col]     = cacc[u][2];
                g_ctx[(tok0 + r0 + 8) * 128 + col + 1] = cacc[u][3];
            }
        }
    }
}

// ---------------- launch ----------------
extern "C" void kernel_launch(void* const* d_in, const int* in_sizes, int n_in,
                              void* d_out, int out_size) {
    const float* x      = (const float*)d_in[0];
    const float* mask   = (const float*)d_in[1];
    const float* qkv_w  = (const float*)d_in[2];
    const float* qkv_b  = (const float*)d_in[3];
    const float* proj_w = (const float*)d_in[4];
    const float* proj_b = (const float*)d_in[5];
    const float* tbl    = (const float*)d_in[6];
    const int*   idx    = (const int*)d_in[7];

    cudaFuncSetAttribute(gemm_tf32_kernel,
                         cudaFuncAttributeMaxDynamicSharedMemorySize, GEMM_SMEM);
    cudaFuncSetAttribute(attn_kernel,
                         cudaFuncAttributeMaxDynamicSharedMemorySize, ATTN_SMEM);

    float* qkv_s; cudaGetSymbolAddress((void**)&qkv_s, g_qkv);
    float* ctx_s; cudaGetSymbolAddress((void**)&ctx_s, g_ctx);

    // K0: fused bias+mask
    biasfuse_kernel<<<2401, 256>>>(tbl, idx, mask);

    // K1: qkv GEMM (M=200704, N=384): A resident, 6 weight chunks streamed
    gemm_tf32_kernel<<<1568, 256, GEMM_SMEM>>>(x, qkv_w, qkv_b, qkv_s, 384, 6, 1);

    // K2: attention
    {
        dim3 grid(4096, 2);
        attn_kernel<<<grid, 256, ATTN_SMEM>>>();
    }

    // K3: proj GEMM (M=200704, N=128): 2 weight chunks
    gemm_tf32_kernel<<<1568, 256, GEMM_SMEM>>>(ctx_s, proj_w, proj_b,
                                               (float*)d_out, 128, 2, 0);
}

// round 8
// speedup vs baseline: 1.6165x; 1.0565x over previous
#include <cuda_runtime.h>

// Swin window attention, 4-kernel split:
//  K0: fuse rel-pos bias + shift mask into g_bm[64][4][49][49]
//  K1: qkv GEMM  (M=200704, N=384, K=128) + bias, q pre-scaled -> g_qkv
//  K2: per-(window, head-pair) attention -> g_ctx   (single-barrier, warp-pipelined)
//  K3: proj GEMM (M=200704, N=128, K=128) + bias -> out
// All GEMMs: mma.sync.m16n8k8 tf32, fragments via ldmatrix.

constexpr int NTOK = 49;
constexpr int NHD  = 4;
constexpr float SCALE = 0.17677669529663687f; // 32^-0.5
constexpr long long TOK = 200704ll;           // 4096 * 49

__device__ float g_qkv[TOK * 384];            // qkv activations (f32)
__device__ float g_ctx[TOK * 128];            // attention context (f32)
__device__ float g_bm[64 * 4 * 49 * 49 + 64]; // fused bias+mask (padded)

// ---------------- helpers ----------------
__device__ __forceinline__ unsigned f2tf(float x) {
    unsigned r;
    asm("cvt.rna.tf32.f32 %0, %1;" : "=r"(r) : "f"(x));
    return r;
}
__device__ __forceinline__ float4 f2tf4(float4 v) {
    float4 t;
    t.x = __uint_as_float(f2tf(v.x));
    t.y = __uint_as_float(f2tf(v.y));
    t.z = __uint_as_float(f2tf(v.z));
    t.w = __uint_as_float(f2tf(v.w));
    return t;
}
__device__ __forceinline__ void mma8(float c[4],
                                     unsigned a0, unsigned a1, unsigned a2, unsigned a3,
                                     unsigned b0, unsigned b1) {
    asm volatile(
        "mma.sync.aligned.m16n8k8.row.col.f32.tf32.tf32.f32 "
        "{%0,%1,%2,%3},{%4,%5,%6,%7},{%8,%9},{%0,%1,%2,%3};"
        : "+f"(c[0]), "+f"(c[1]), "+f"(c[2]), "+f"(c[3])
        : "r"(a0), "r"(a1), "r"(a2), "r"(a3), "r"(b0), "r"(b1));
}
__device__ __forceinline__ unsigned sptr(const float* p) {
    return (unsigned)__cvta_generic_to_shared(p);
}
__device__ __forceinline__ void ldA(unsigned r[4], const float* base, int L) {
    int lane = threadIdx.x & 31;
    const float* p = base + ((lane & 7) + ((lane & 8) ? 8 : 0)) * L + ((lane & 16) ? 4 : 0);
    unsigned a = sptr(p);
    asm volatile("ldmatrix.sync.aligned.m8n8.x4.shared.b16 {%0,%1,%2,%3}, [%4];"
                 : "=r"(r[0]), "=r"(r[1]), "=r"(r[2]), "=r"(r[3]) : "r"(a));
}
__device__ __forceinline__ void ldB(unsigned r[2], const float* base, int L) {
    int lane = threadIdx.x & 31;
    const float* p = base + (lane & 7) * L + ((lane & 8) ? 4 : 0);
    unsigned a = sptr(p);
    asm volatile("ldmatrix.sync.aligned.m8n8.x2.shared.b16 {%0,%1}, [%2];"
                 : "=r"(r[0]), "=r"(r[1]) : "r"(a));
}
__device__ __forceinline__ unsigned ldsm(const float* p) { return __float_as_uint(*p); }

// ---------------- K0: fused bias+mask table ----------------
__global__ void biasfuse_kernel(const float* __restrict__ tbl,
                                const int*   __restrict__ idx,
                                const float* __restrict__ mask) {
    long i = (long)blockIdx.x * 256 + threadIdx.x;   // 64*4*49*49 = 614656 exactly
    int m = (int)(i % 49);
    long r = i / 49;
    int n = (int)(r % 49); r /= 49;
    int h = (int)(r % 4);
    int wn = (int)(r / 4);
    g_bm[i] = __ldg(tbl + __ldg(idx + n * 49 + m) * NHD + h)
            + __ldg(mask + wn * 2401 + n * 49 + m);
}

// ---------------- K1/K3: GEMM  C[M,N] = A[M,128] @ W[N,128]^T + bias ----------------
// A tile (128x128) resident; W streamed in 64-col chunks with register prefetch.
constexpr int GA = 0;                 // A tile 128 x 132
constexpr int GB = 128 * 132;         // B chunk 64 x 132
constexpr int GEMM_SMEM = (128 * 132 + 64 * 132) * 4;   // 101376 B

__global__ __launch_bounds__(256, 2)
void gemm_tf32_kernel(const float* __restrict__ A,
                      const float* __restrict__ W,
                      const float* __restrict__ bias,
                      float* __restrict__ C,
                      int ldc, int n_chunks, int qscale) {
    extern __shared__ float sm[];
    const int tid = threadIdx.x, lane = tid & 31, w = tid >> 5;
    const int wm = w & 3, wn = w >> 2;
    const int ar = lane >> 2, ac = lane & 3;
    const long mt = blockIdx.x;

    // stage A (128x128 = 4096 float4 -> tf32, STS.128), once
    {
        const float4* ag = (const float4*)(A + mt * 128 * 128);
        #pragma unroll
        for (int i = 0; i < 16; ++i) {
            int j = tid + i * 256;
            int r = j >> 5, c4 = j & 31;
            *(float4*)(sm + GA + r * 132 + c4 * 4) = f2tf4(__ldg(ag + j));
        }
    }
    // stage B chunk 0 (64x128 = 2048 float4)
    {
        const float4* wg = (const float4*)W;
        #pragma unroll
        for (int i = 0; i < 8; ++i) {
            int j = tid + i * 256;
            int r = j >> 5, c4 = j & 31;
            *(float4*)(sm + GB + r * 132 + c4 * 4) = f2tf4(__ldg(wg + j));
        }
    }
    __syncthreads();

    for (int nt = 0; nt < n_chunks; ++nt) {
        // prefetch next B chunk into registers (overlaps with compute below)
        float4 breg[8];
        const bool pf = (nt + 1 < n_chunks);
        if (pf) {
            const float4* wg = (const float4*)(W + (long)(nt + 1) * 64 * 128);
            #pragma unroll
            for (int i = 0; i < 8; ++i) breg[i] = __ldg(wg + tid + i * 256);
        }

        // compute 128x64 tile
        float acc[2][4][4];
        #pragma unroll
        for (int hf = 0; hf < 2; ++hf)
            #pragma unroll
            for (int t = 0; t < 4; ++t)
                #pragma unroll
                for (int j = 0; j < 4; ++j) acc[hf][t][j] = 0.f;

        #pragma unroll 4
        for (int k0 = 0; k0 < 128; k0 += 8) {
            unsigned a0[4], a1[4];
            ldA(a0, sm + GA + (wm * 32) * 132 + k0, 132);
            ldA(a1, sm + GA + (wm * 32 + 16) * 132 + k0, 132);
            #pragma unroll
            for (int t = 0; t < 4; ++t) {
                unsigned bb[2];
                ldB(bb, sm + GB + (wn * 32 + t * 8) * 132 + k0, 132);
                mma8(acc[0][t], a0[0], a0[1], a0[2], a0[3], bb[0], bb[1]);
                mma8(acc[1][t], a1[0], a1[1], a1[2], a1[3], bb[0], bb[1]);
            }
        }

        // epilogue: bias (+ q scale) and store
        #pragma unroll
        for (int hf = 0; hf < 2; ++hf)
            #pragma unroll
            for (int t = 0; t < 4; ++t) {
                int col = nt * 64 + wn * 32 + t * 8 + 2 * ac;
                float sc = (qscale && col < 128) ? SCALE : 1.f;
                float b0v = __ldg(bias + col);
                float b1v = __ldg(bias + col + 1);
                long row = mt * 128 + wm * 32 + hf * 16 + ar;
                C[row * ldc + col]            = (acc[hf][t][0] + b0v) * sc;
                C[row * ldc + col + 1]        = (acc[hf][t][1] + b1v) * sc;
                C[(row + 8) * ldc + col]      = (acc[hf][t][2] + b0v) * sc;
                C[(row + 8) * ldc + col + 1]  = (acc[hf][t][3] + b1v) * sc;
            }

        if (pf) {
            __syncthreads();   // all warps done reading current B
            #pragma unroll
            for (int i = 0; i < 8; ++i) {
                int j = tid + i * 256;
                int r = j >> 5, c4 = j & 31;
                *(float4*)(sm + GB + r * 132 + c4 * 4) = f2tf4(breg[i]);
            }
            __syncthreads();   // new B visible
        }
    }
}

// ---------------- K2: attention per (window, head-pair) ----------------
// Single CTA-wide barrier (post-staging); all later phases are warp-private
// (warp wm owns score/softmax/PV rows [16*wm, 16*wm+16)), sync via __syncwarp.
constexpr int QS2 = 0;                   // 64 x 68
constexpr int KS2 = QS2 + 64 * 68;
constexpr int VS2 = KS2 + 64 * 68;
constexpr int SS2 = VS2 + 64 * 68;       // 2 x (64 x 68) score buffers
constexpr int BMS = SS2 + 2 * 64 * 68;   // 2 x 2404 fused bias+mask
constexpr int ATTN_FLOATS = BMS + 2 * 2404;
constexpr int ATTN_SMEM = ATTN_FLOATS * 4;   // 106272 B -> 2 CTAs/SM

__global__ __launch_bounds__(256, 2)
void attn_kernel() {
    extern __shared__ float sm[];
    const int tid = threadIdx.x, lane = tid & 31, w = tid >> 5;
    const int wm = w & 3, hh = w >> 2;
    const int ar = lane >> 2, ac = lane & 3;
    const int win = blockIdx.x, hp = blockIdx.y;
    const long tok0 = (long)win * NTOK;

    // ---- staging phase (the only CTA-wide barrier follows it) ----
    // zero pad rows (49..63) x 64 cols of q,k,v
    {
        const float4 z = make_float4(0.f, 0.f, 0.f, 0.f);
        for (int i = tid; i < 15 * 16 * 3; i += 256) {
            int buf = i / (15 * 16);
            int rem = i - buf * 15 * 16;
            int r = 49 + (rem >> 4), c4 = rem & 15;
            *(float4*)(sm + buf * (64 * 68) + r * 68 + c4 * 4) = z;
        }
    }
    // q,k,v (49 rows x 64 cols each) as tf32, stride 68
    {
        const float* qb = g_qkv + tok0 * 384 + hp * 64;
        const float* kb = qb + 128;
        const float* vb = qb + 256;
        for (int i = tid; i < NTOK * 16; i += 256) {
            int r = i >> 4, c4 = (i & 15) * 4;
            long off = (long)r * 384 + c4;
            *(float4*)(sm + QS2 + r * 68 + c4) = f2tf4(__ldg((const float4*)(qb + off)));
            *(float4*)(sm + KS2 + r * 68 + c4) = f2tf4(__ldg((const float4*)(kb + off)));
            *(float4*)(sm + VS2 + r * 68 + c4) = f2tf4(__ldg((const float4*)(vb + off)));
        }
    }
    // fused bias+mask for this head pair (2 x 2401 floats, contiguous in g_bm)
    {
        const float* bm0 = g_bm + (size_t)((win & 63) * 4 + hp * 2) * 2401;
        for (int i = tid; i < 2401; i += 256) {
            sm[BMS + i]        = __ldg(bm0 + i);
            sm[BMS + 2404 + i] = __ldg(bm0 + 2401 + i);
        }
    }
    __syncthreads();

    float* sb = sm + SS2 + hh * (64 * 68);

    // ---- scores S = Q_h @ K_h^T (64x64, K=32); warp tile 16x64 ----
    {
        float sacc[8][4];
        #pragma unroll
        for (int t = 0; t < 8; ++t)
            #pragma unroll
            for (int j = 0; j < 4; ++j) sacc[t][j] = 0.f;

        #pragma unroll
        for (int kk = 0; kk < 4; ++kk) {
            int k0 = hh * 32 + kk * 8;
            unsigned a[4];
            ldA(a, sm + QS2 + (wm * 16) * 68 + k0, 68);
            #pragma unroll
            for (int t = 0; t < 8; ++t) {
                unsigned bb[2];
                ldB(bb, sm + KS2 + (t * 8) * 68 + k0, 68);
                mma8(sacc[t], a[0], a[1], a[2], a[3], bb[0], bb[1]);
            }
        }
        #pragma unroll
        for (int t = 0; t < 8; ++t) {
            int m0 = t * 8 + 2 * ac;
            int r0 = wm * 16 + ar;
            sb[r0 * 68 + m0]           = sacc[t][0];
            sb[r0 * 68 + m0 + 1]       = sacc[t][1];
            sb[(r0 + 8) * 68 + m0]     = sacc[t][2];
            sb[(r0 + 8) * 68 + m0 + 1] = sacc[t][3];
        }
    }
    __syncwarp();

    // ---- softmax (warp-private rows), bias+mask from smem ----
    {
        const float* bmh = sm + BMS + hh * 2404;
        #pragma unroll 4
        for (int rr = 0; rr < 16; ++rr) {
            int n = wm * 16 + rr;
            float s0 = -1e30f, s1 = -1e30f;
            if (n < NTOK) {
                if (lane < NTOK)
                    s0 = sb[n * 68 + lane] + bmh[n * 49 + lane];
                int m1 = lane + 32;
                if (m1 < NTOK)
                    s1 = sb[n * 68 + m1] + bmh[n * 49 + m1];
            }
            float mx = fmaxf(s0, s1);
            #pragma unroll
            for (int o = 16; o; o >>= 1) mx = fmaxf(mx, __shfl_xor_sync(0xffffffffu, mx, o));
            float e0 = (s0 > -1e29f) ? __expf(s0 - mx) : 0.f;
            float e1 = (s1 > -1e29f) ? __expf(s1 - mx) : 0.f;
            float sum = e0 + e1;
            #pragma unroll
            for (int o = 16; o; o >>= 1) sum += __shfl_xor_sync(0xffffffffu, sum, o);
            if (n < NTOK) {
                float inv = __fdividef(1.f, sum);
                sb[n * 68 + lane]      = __uint_as_float(f2tf(e0 * inv));
                sb[n * 68 + lane + 32] = __uint_as_float(f2tf(e1 * inv));
            } else {
                sb[n * 68 + lane]      = 0.f;
                sb[n * 68 + lane + 32] = 0.f;
            }
        }
    }
    __syncwarp();

    // ---- ctx = P @ V_h (64x32, K=64); warp tile 16x32 ----
    {
        const int h = hp * 2 + hh;
        float cacc[4][4];
        #pragma unroll
        for (int u = 0; u < 4; ++u)
            #pragma unroll
            for (int j = 0; j < 4; ++j) cacc[u][j] = 0.f;

        #pragma unroll
        for (int k0 = 0; k0 < 64; k0 += 8) {
            unsigned a[4];
            ldA(a, sb + (wm * 16) * 68 + k0, 68);
            #pragma unroll
            for (int u = 0; u < 4; ++u) {
                int n0 = hh * 32 + u * 8;
                unsigned b0 = ldsm(sm + VS2 + (k0 + ac) * 68 + n0 + ar);
                unsigned b1 = ldsm(sm + VS2 + (k0 + 4 + ac) * 68 + n0 + ar);
                mma8(cacc[u], a[0], a[1], a[2], a[3], b0, b1);
            }
        }
        #pragma unroll
        for (int u = 0; u < 4; ++u) {
            int col = h * 32 + u * 8 + 2 * ac;
            int r0 = wm * 16 + ar;
            if (r0 < NTOK) {
                g_ctx[(tok0 + r0) * 128 + col]     = cacc[u][0];
                g_ctx[(tok0 + r0) * 128 + col + 1] = cacc[u][1];
            }
            if (r0 + 8 < NTOK) {
                g_ctx[(tok0 + r0 + 8) * 128 + col]     = cacc[u][2];
                g_ctx[(tok0 + r0 + 8) * 128 + col + 1] = cacc[u][3];
            }
        }
    }
}

// ---------------- launch ----------------
extern "C" void kernel_launch(void* const* d_in, const int* in_sizes, int n_in,
                              void* d_out, int out_size) {
    const float* x      = (const float*)d_in[0];
    const float* mask   = (const float*)d_in[1];
    const float* qkv_w  = (const float*)d_in[2];
    const float* qkv_b  = (const float*)d_in[3];
    const float* proj_w = (const float*)d_in[4];
    const float* proj_b = (const float*)d_in[5];
    const float* tbl    = (const float*)d_in[6];
    const int*   idx    = (const int*)d_in[7];

    cudaFuncSetAttribute(gemm_tf32_kernel,
                         cudaFuncAttributeMaxDynamicSharedMemorySize, GEMM_SMEM);
    cudaFuncSetAttribute(attn_kernel,
                         cudaFuncAttributeMaxDynamicSharedMemorySize, ATTN_SMEM);

    float* qkv_s; cudaGetSymbolAddress((void**)&qkv_s, g_qkv);
    float* ctx_s; cudaGetSymbolAddress((void**)&ctx_s, g_ctx);

    // K0: fused bias+mask
    biasfuse_kernel<<<2401, 256>>>(tbl, idx, mask);

    // K1: qkv GEMM (M=200704, N=384): A resident, 6 weight chunks streamed
    gemm_tf32_kernel<<<1568, 256, GEMM_SMEM>>>(x, qkv_w, qkv_b, qkv_s, 384, 6, 1);

    // K2: attention
    {
        dim3 grid(4096, 2);
        attn_kernel<<<grid, 256, ATTN_SMEM>>>();
    }

    // K3: proj GEMM (M=200704, N=128): 2 weight chunks
    gemm_tf32_kernel<<<1568, 256, GEMM_SMEM>>>(ctx_s, proj_w, proj_b,
                                               (float*)d_out, 128, 2, 0);
}

// round 9
// speedup vs baseline: 1.7731x; 1.0969x over previous
#include <cuda_runtime.h>

// Swin window attention, 4-kernel split:
//  K0: fuse rel-pos bias + shift mask into g_bm[64][4][49][49]
//  K1: qkv GEMM  (M=200704, N=384, K=128) + bias, q pre-scaled -> g_qkv
//  K2: per-(window, head) attention -> g_ctx  (128 thr, 5 CTAs/SM)
//  K3: proj GEMM (M=200704, N=128, K=128) + bias -> out
// All GEMMs: mma.sync.m16n8k8 tf32, fragments via ldmatrix.

constexpr int NTOK = 49;
constexpr int NHD  = 4;
constexpr float SCALE = 0.17677669529663687f; // 32^-0.5
constexpr long long TOK = 200704ll;           // 4096 * 49

__device__ float g_qkv[TOK * 384];            // qkv activations (f32)
__device__ float g_ctx[TOK * 128];            // attention context (f32)
__device__ float g_bm[64 * 4 * 49 * 49 + 64]; // fused bias+mask (padded)

// ---------------- helpers ----------------
__device__ __forceinline__ unsigned f2tf(float x) {
    unsigned r;
    asm("cvt.rna.tf32.f32 %0, %1;" : "=r"(r) : "f"(x));
    return r;
}
__device__ __forceinline__ float4 f2tf4(float4 v) {
    float4 t;
    t.x = __uint_as_float(f2tf(v.x));
    t.y = __uint_as_float(f2tf(v.y));
    t.z = __uint_as_float(f2tf(v.z));
    t.w = __uint_as_float(f2tf(v.w));
    return t;
}
__device__ __forceinline__ void mma8(float c[4],
                                     unsigned a0, unsigned a1, unsigned a2, unsigned a3,
                                     unsigned b0, unsigned b1) {
    asm volatile(
        "mma.sync.aligned.m16n8k8.row.col.f32.tf32.tf32.f32 "
        "{%0,%1,%2,%3},{%4,%5,%6,%7},{%8,%9},{%0,%1,%2,%3};"
        : "+f"(c[0]), "+f"(c[1]), "+f"(c[2]), "+f"(c[3])
        : "r"(a0), "r"(a1), "r"(a2), "r"(a3), "r"(b0), "r"(b1));
}
__device__ __forceinline__ unsigned sptr(const float* p) {
    return (unsigned)__cvta_generic_to_shared(p);
}
__device__ __forceinline__ void ldA(unsigned r[4], const float* base, int L) {
    int lane = threadIdx.x & 31;
    const float* p = base + ((lane & 7) + ((lane & 8) ? 8 : 0)) * L + ((lane & 16) ? 4 : 0);
    unsigned a = sptr(p);
    asm volatile("ldmatrix.sync.aligned.m8n8.x4.shared.b16 {%0,%1,%2,%3}, [%4];"
                 : "=r"(r[0]), "=r"(r[1]), "=r"(r[2]), "=r"(r[3]) : "r"(a));
}
__device__ __forceinline__ void ldB(unsigned r[2], const float* base, int L) {
    int lane = threadIdx.x & 31;
    const float* p = base + (lane & 7) * L + ((lane & 8) ? 4 : 0);
    unsigned a = sptr(p);
    asm volatile("ldmatrix.sync.aligned.m8n8.x2.shared.b16 {%0,%1}, [%2];"
                 : "=r"(r[0]), "=r"(r[1]) : "r"(a));
}
__device__ __forceinline__ unsigned ldsm(const float* p) { return __float_as_uint(*p); }

// ---------------- K0: fused bias+mask table ----------------
__global__ void biasfuse_kernel(const float* __restrict__ tbl,
                                const int*   __restrict__ idx,
                                const float* __restrict__ mask) {
    long i = (long)blockIdx.x * 256 + threadIdx.x;   // 64*4*49*49 = 614656 exactly
    int m = (int)(i % 49);
    long r = i / 49;
    int n = (int)(r % 49); r /= 49;
    int h = (int)(r % 4);
    int wn = (int)(r / 4);
    g_bm[i] = __ldg(tbl + __ldg(idx + n * 49 + m) * NHD + h)
            + __ldg(mask + wn * 2401 + n * 49 + m);
}

// ---------------- K1/K3: GEMM  C[M,N] = A[M,128] @ W[N,128]^T + bias ----------------
// A tile (128x128) resident; W streamed in 64-col chunks with register prefetch.
constexpr int GA = 0;                 // A tile 128 x 132
constexpr int GB = 128 * 132;         // B chunk 64 x 132
constexpr int GEMM_SMEM = (128 * 132 + 64 * 132) * 4;   // 101376 B

__global__ __launch_bounds__(256, 2)
void gemm_tf32_kernel(const float* __restrict__ A,
                      const float* __restrict__ W,
                      const float* __restrict__ bias,
                      float* __restrict__ C,
                      int ldc, int n_chunks, int qscale) {
    extern __shared__ float sm[];
    const int tid = threadIdx.x, lane = tid & 31, w = tid >> 5;
    const int wm = w & 3, wn = w >> 2;
    const int ar = lane >> 2, ac = lane & 3;
    const long mt = blockIdx.x;

    // stage A (128x128 = 4096 float4 -> tf32, STS.128), once
    {
        const float4* ag = (const float4*)(A + mt * 128 * 128);
        #pragma unroll
        for (int i = 0; i < 16; ++i) {
            int j = tid + i * 256;
            int r = j >> 5, c4 = j & 31;
            *(float4*)(sm + GA + r * 132 + c4 * 4) = f2tf4(__ldg(ag + j));
        }
    }
    // stage B chunk 0 (64x128 = 2048 float4)
    {
        const float4* wg = (const float4*)W;
        #pragma unroll
        for (int i = 0; i < 8; ++i) {
            int j = tid + i * 256;
            int r = j >> 5, c4 = j & 31;
            *(float4*)(sm + GB + r * 132 + c4 * 4) = f2tf4(__ldg(wg + j));
        }
    }
    __syncthreads();

    for (int nt = 0; nt < n_chunks; ++nt) {
        float4 breg[8];
        const bool pf = (nt + 1 < n_chunks);
        if (pf) {
            const float4* wg = (const float4*)(W + (long)(nt + 1) * 64 * 128);
            #pragma unroll
            for (int i = 0; i < 8; ++i) breg[i] = __ldg(wg + tid + i * 256);
        }

        float acc[2][4][4];
        #pragma unroll
        for (int hf = 0; hf < 2; ++hf)
            #pragma unroll
            for (int t = 0; t < 4; ++t)
                #pragma unroll
                for (int j = 0; j < 4; ++j) acc[hf][t][j] = 0.f;

        #pragma unroll 4
        for (int k0 = 0; k0 < 128; k0 += 8) {
            unsigned a0[4], a1[4];
            ldA(a0, sm + GA + (wm * 32) * 132 + k0, 132);
            ldA(a1, sm + GA + (wm * 32 + 16) * 132 + k0, 132);
            #pragma unroll
            for (int t = 0; t < 4; ++t) {
                unsigned bb[2];
                ldB(bb, sm + GB + (wn * 32 + t * 8) * 132 + k0, 132);
                mma8(acc[0][t], a0[0], a0[1], a0[2], a0[3], bb[0], bb[1]);
                mma8(acc[1][t], a1[0], a1[1], a1[2], a1[3], bb[0], bb[1]);
            }
        }

        #pragma unroll
        for (int hf = 0; hf < 2; ++hf)
            #pragma unroll
            for (int t = 0; t < 4; ++t) {
                int col = nt * 64 + wn * 32 + t * 8 + 2 * ac;
                float sc = (qscale && col < 128) ? SCALE : 1.f;
                float b0v = __ldg(bias + col);
                float b1v = __ldg(bias + col + 1);
                long row = mt * 128 + wm * 32 + hf * 16 + ar;
                C[row * ldc + col]            = (acc[hf][t][0] + b0v) * sc;
                C[row * ldc + col + 1]        = (acc[hf][t][1] + b1v) * sc;
                C[(row + 8) * ldc + col]      = (acc[hf][t][2] + b0v) * sc;
                C[(row + 8) * ldc + col + 1]  = (acc[hf][t][3] + b1v) * sc;
            }

        if (pf) {
            __syncthreads();
            #pragma unroll
            for (int i = 0; i < 8; ++i) {
                int j = tid + i * 256;
                int r = j >> 5, c4 = j & 31;
                *(float4*)(sm + GB + r * 132 + c4 * 4) = f2tf4(breg[i]);
            }
            __syncthreads();
        }
    }
}

// ---------------- K2: attention per (window, head) ----------------
// 128 thr / 4 warps; warp wm owns rows [16*wm, 16*wm+16) of scores/softmax/PV.
// smem 46080 B -> 5 CTAs/SM.
constexpr int QS3 = 0;                   // Q 64 x 36
constexpr int KS3 = QS3 + 64 * 36;       // K 64 x 36
constexpr int VS3 = KS3 + 64 * 36;       // V 64 x 40 (conflict-free PV loads)
constexpr int SS3 = VS3 + 64 * 40;       // S 64 x 68
constexpr int ATTN_SMEM = (SS3 + 64 * 68) * 4;   // 46080 B

__global__ __launch_bounds__(128, 5)
void attn_kernel() {
    extern __shared__ float sm[];
    const int tid = threadIdx.x, lane = tid & 31, wm = tid >> 5;
    const int ar = lane >> 2, ac = lane & 3;
    const int win = blockIdx.x, h = blockIdx.y;
    const long tok0 = (long)win * NTOK;

    // zero V pad rows (49..63) x 32 cols (only V needs it: P pad cols are exact 0,
    // but 0 * NaN would poison PV; Q/K pad garbage is overwritten before use)
    {
        const float4 z = make_float4(0.f, 0.f, 0.f, 0.f);
        for (int i = tid; i < 15 * 8; i += 128) {
            int r = 49 + (i >> 3), c4 = i & 7;
            *(float4*)(sm + VS3 + r * 40 + c4 * 4) = z;
        }
    }
    // stage q,k,v (49 rows x 32 cols each) as tf32
    {
        const float* qb = g_qkv + tok0 * 384 + h * 32;
        const float* kb = qb + 128;
        const float* vb = qb + 256;
        for (int i = tid; i < NTOK * 8; i += 128) {
            int r = i >> 3, c4 = (i & 7) * 4;
            long off = (long)r * 384 + c4;
            *(float4*)(sm + QS3 + r * 36 + c4) = f2tf4(__ldg((const float4*)(qb + off)));
            *(float4*)(sm + KS3 + r * 36 + c4) = f2tf4(__ldg((const float4*)(kb + off)));
            *(float4*)(sm + VS3 + r * 40 + c4) = f2tf4(__ldg((const float4*)(vb + off)));
        }
    }
    __syncthreads();

    float* sb = sm + SS3;

    // ---- scores S = Q_h @ K_h^T (64x64, K=32); warp tile 16x64 ----
    {
        float sacc[8][4];
        #pragma unroll
        for (int t = 0; t < 8; ++t)
            #pragma unroll
            for (int j = 0; j < 4; ++j) sacc[t][j] = 0.f;

        #pragma unroll
        for (int kk = 0; kk < 4; ++kk) {
            int k0 = kk * 8;
            unsigned a[4];
            ldA(a, sm + QS3 + (wm * 16) * 36 + k0, 36);
            #pragma unroll
            for (int t = 0; t < 8; ++t) {
                unsigned bb[2];
                ldB(bb, sm + KS3 + (t * 8) * 36 + k0, 36);
                mma8(sacc[t], a[0], a[1], a[2], a[3], bb[0], bb[1]);
            }
        }
        #pragma unroll
        for (int t = 0; t < 8; ++t) {
            int m0 = t * 8 + 2 * ac;
            int r0 = wm * 16 + ar;
            sb[r0 * 68 + m0]           = sacc[t][0];
            sb[r0 * 68 + m0 + 1]       = sacc[t][1];
            sb[(r0 + 8) * 68 + m0]     = sacc[t][2];
            sb[(r0 + 8) * 68 + m0 + 1] = sacc[t][3];
        }
    }
    __syncwarp();

    // ---- softmax, no max-subtraction (scores are O(1)-scale; shift-invariant) ----
    {
        const float* bmh = g_bm + (size_t)((win & 63) * 4 + h) * 2401;
        #pragma unroll 4
        for (int rr = 0; rr < 16; ++rr) {
            int n = wm * 16 + rr;
            if (n < NTOK) {
                float s0 = sb[n * 68 + lane] + __ldg(bmh + n * 49 + lane);
                float s1 = -1e30f;
                int m1 = lane + 32;
                if (m1 < NTOK)
                    s1 = sb[n * 68 + m1] + __ldg(bmh + n * 49 + m1);
                float e0 = __expf(s0);     // mask -100 -> ~0; sentinel -> 0
                float e1 = __expf(s1);
                float sum = e0 + e1;
                #pragma unroll
                for (int o = 16; o; o >>= 1) sum += __shfl_xor_sync(0xffffffffu, sum, o);
                float inv = __fdividef(1.f, sum);
                sb[n * 68 + lane]      = __uint_as_float(f2tf(e0 * inv));
                sb[n * 68 + lane + 32] = __uint_as_float(f2tf(e1 * inv));
            } else {
                sb[n * 68 + lane]      = 0.f;
                sb[n * 68 + lane + 32] = 0.f;
            }
        }
    }
    __syncwarp();

    // ---- ctx = P @ V_h (64x32, K=64); warp tile 16x32 ----
    {
        float cacc[4][4];
        #pragma unroll
        for (int u = 0; u < 4; ++u)
            #pragma unroll
            for (int j = 0; j < 4; ++j) cacc[u][j] = 0.f;

        #pragma unroll
        for (int k0 = 0; k0 < 64; k0 += 8) {
            unsigned a[4];
            ldA(a, sb + (wm * 16) * 68 + k0, 68);
            #pragma unroll
            for (int u = 0; u < 4; ++u) {
                int n0 = u * 8;
                unsigned b0 = ldsm(sm + VS3 + (k0 + ac) * 40 + n0 + ar);
                unsigned b1 = ldsm(sm + VS3 + (k0 + 4 + ac) * 40 + n0 + ar);
                mma8(cacc[u], a[0], a[1], a[2], a[3], b0, b1);
            }
        }
        #pragma unroll
        for (int u = 0; u < 4; ++u) {
            int col = h * 32 + u * 8 + 2 * ac;
            int r0 = wm * 16 + ar;
            if (r0 < NTOK)
                *(float2*)(g_ctx + (tok0 + r0) * 128 + col) =
                    make_float2(cacc[u][0], cacc[u][1]);
            if (r0 + 8 < NTOK)
                *(float2*)(g_ctx + (tok0 + r0 + 8) * 128 + col) =
                    make_float2(cacc[u][2], cacc[u][3]);
        }
    }
}

// ---------------- launch ----------------
extern "C" void kernel_launch(void* const* d_in, const int* in_sizes, int n_in,
                              void* d_out, int out_size) {
    const float* x      = (const float*)d_in[0];
    const float* mask   = (const float*)d_in[1];
    const float* qkv_w  = (const float*)d_in[2];
    const float* qkv_b  = (const float*)d_in[3];
    const float* proj_w = (const float*)d_in[4];
    const float* proj_b = (const float*)d_in[5];
    const float* tbl    = (const float*)d_in[6];
    const int*   idx    = (const int*)d_in[7];

    cudaFuncSetAttribute(gemm_tf32_kernel,
                         cudaFuncAttributeMaxDynamicSharedMemorySize, GEMM_SMEM);
    cudaFuncSetAttribute(attn_kernel,
                         cudaFuncAttributeMaxDynamicSharedMemorySize, ATTN_SMEM);

    float* qkv_s; cudaGetSymbolAddress((void**)&qkv_s, g_qkv);
    float* ctx_s; cudaGetSymbolAddress((void**)&ctx_s, g_ctx);

    // K0: fused bias+mask
    biasfuse_kernel<<<2401, 256>>>(tbl, idx, mask);

    // K1: qkv GEMM (M=200704, N=384): A resident, 6 weight chunks streamed
    gemm_tf32_kernel<<<1568, 256, GEMM_SMEM>>>(x, qkv_w, qkv_b, qkv_s, 384, 6, 1);

    // K2: attention, one (window, head) per CTA
    {
        dim3 grid(4096, 4);
        attn_kernel<<<grid, 128, ATTN_SMEM>>>();
    }

    // K3: proj GEMM (M=200704, N=128): 2 weight chunks
    gemm_tf32_kernel<<<1568, 256, GEMM_SMEM>>>(ctx_s, proj_w, proj_b,
                                               (float*)d_out, 128, 2, 0);
}

// round 10
// speedup vs baseline: 2.2844x; 1.2884x over previous
#include <cuda_runtime.h>

// Swin window attention, 4-kernel split:
//  K0: fuse rel-pos bias + shift mask into g_bm[64][4][49][49]
//  K1: qkv GEMM  (M=200704, N=384, K=128) + bias, q pre-scaled -> g_qkv
//  K2: per-(window, head) attention -> g_ctx  (register-domain softmax, no S buffer)
//  K3: proj GEMM (M=200704, N=128, K=128) + bias -> out
// All GEMMs: mma.sync.m16n8k8 tf32, fragments via ldmatrix.

constexpr int NTOK = 49;
constexpr int NHD  = 4;
constexpr float SCALE = 0.17677669529663687f; // 32^-0.5
constexpr long long TOK = 200704ll;           // 4096 * 49

__device__ float g_qkv[TOK * 384];            // qkv activations (f32)
__device__ float g_ctx[TOK * 128];            // attention context (f32)
__device__ float g_bm[64 * 4 * 49 * 49 + 64]; // fused bias+mask (padded)

// ---------------- helpers ----------------
__device__ __forceinline__ unsigned f2tf(float x) {
    unsigned r;
    asm("cvt.rna.tf32.f32 %0, %1;" : "=r"(r) : "f"(x));
    return r;
}
__device__ __forceinline__ float4 f2tf4(float4 v) {
    float4 t;
    t.x = __uint_as_float(f2tf(v.x));
    t.y = __uint_as_float(f2tf(v.y));
    t.z = __uint_as_float(f2tf(v.z));
    t.w = __uint_as_float(f2tf(v.w));
    return t;
}
__device__ __forceinline__ void mma8(float c[4],
                                     unsigned a0, unsigned a1, unsigned a2, unsigned a3,
                                     unsigned b0, unsigned b1) {
    asm volatile(
        "mma.sync.aligned.m16n8k8.row.col.f32.tf32.tf32.f32 "
        "{%0,%1,%2,%3},{%4,%5,%6,%7},{%8,%9},{%0,%1,%2,%3};"
        : "+f"(c[0]), "+f"(c[1]), "+f"(c[2]), "+f"(c[3])
        : "r"(a0), "r"(a1), "r"(a2), "r"(a3), "r"(b0), "r"(b1));
}
__device__ __forceinline__ unsigned sptr(const float* p) {
    return (unsigned)__cvta_generic_to_shared(p);
}
__device__ __forceinline__ void ldA(unsigned r[4], const float* base, int L) {
    int lane = threadIdx.x & 31;
    const float* p = base + ((lane & 7) + ((lane & 8) ? 8 : 0)) * L + ((lane & 16) ? 4 : 0);
    unsigned a = sptr(p);
    asm volatile("ldmatrix.sync.aligned.m8n8.x4.shared.b16 {%0,%1,%2,%3}, [%4];"
                 : "=r"(r[0]), "=r"(r[1]), "=r"(r[2]), "=r"(r[3]) : "r"(a));
}
__device__ __forceinline__ void ldB(unsigned r[2], const float* base, int L) {
    int lane = threadIdx.x & 31;
    const float* p = base + (lane & 7) * L + ((lane & 8) ? 4 : 0);
    unsigned a = sptr(p);
    asm volatile("ldmatrix.sync.aligned.m8n8.x2.shared.b16 {%0,%1}, [%2];"
                 : "=r"(r[0]), "=r"(r[1]) : "r"(a));
}
__device__ __forceinline__ unsigned ldsm(const float* p) { return __float_as_uint(*p); }

// ---------------- K0: fused bias+mask table ----------------
__global__ void biasfuse_kernel(const float* __restrict__ tbl,
                                const int*   __restrict__ idx,
                                const float* __restrict__ mask) {
    long i = (long)blockIdx.x * 256 + threadIdx.x;   // 64*4*49*49 = 614656 exactly
    int m = (int)(i % 49);
    long r = i / 49;
    int n = (int)(r % 49); r /= 49;
    int h = (int)(r % 4);
    int wn = (int)(r / 4);
    g_bm[i] = __ldg(tbl + __ldg(idx + n * 49 + m) * NHD + h)
            + __ldg(mask + wn * 2401 + n * 49 + m);
}

// ---------------- K1/K3: GEMM  C[M,N] = A[M,128] @ W[N,128]^T + bias ----------------
// A tile (128x128) resident; W streamed in 64-col chunks with register prefetch.
constexpr int GA = 0;                 // A tile 128 x 132
constexpr int GB = 128 * 132;         // B chunk 64 x 132
constexpr int GEMM_SMEM = (128 * 132 + 64 * 132) * 4;   // 101376 B

__global__ __launch_bounds__(256, 2)
void gemm_tf32_kernel(const float* __restrict__ A,
                      const float* __restrict__ W,
                      const float* __restrict__ bias,
                      float* __restrict__ C,
                      int ldc, int n_chunks, int qscale) {
    extern __shared__ float sm[];
    const int tid = threadIdx.x, lane = tid & 31, w = tid >> 5;
    const int wm = w & 3, wn = w >> 2;
    const int ar = lane >> 2, ac = lane & 3;
    const long mt = blockIdx.x;

    // stage A (128x128 = 4096 float4 -> tf32, STS.128), once
    {
        const float4* ag = (const float4*)(A + mt * 128 * 128);
        #pragma unroll
        for (int i = 0; i < 16; ++i) {
            int j = tid + i * 256;
            int r = j >> 5, c4 = j & 31;
            *(float4*)(sm + GA + r * 132 + c4 * 4) = f2tf4(__ldg(ag + j));
        }
    }
    // stage B chunk 0 (64x128 = 2048 float4)
    {
        const float4* wg = (const float4*)W;
        #pragma unroll
        for (int i = 0; i < 8; ++i) {
            int j = tid + i * 256;
            int r = j >> 5, c4 = j & 31;
            *(float4*)(sm + GB + r * 132 + c4 * 4) = f2tf4(__ldg(wg + j));
        }
    }
    __syncthreads();

    for (int nt = 0; nt < n_chunks; ++nt) {
        float4 breg[8];
        const bool pf = (nt + 1 < n_chunks);
        if (pf) {
            const float4* wg = (const float4*)(W + (long)(nt + 1) * 64 * 128);
            #pragma unroll
            for (int i = 0; i < 8; ++i) breg[i] = __ldg(wg + tid + i * 256);
        }

        float acc[2][4][4];
        #pragma unroll
        for (int hf = 0; hf < 2; ++hf)
            #pragma unroll
            for (int t = 0; t < 4; ++t)
                #pragma unroll
                for (int j = 0; j < 4; ++j) acc[hf][t][j] = 0.f;

        #pragma unroll 4
        for (int k0 = 0; k0 < 128; k0 += 8) {
            unsigned a0[4], a1[4];
            ldA(a0, sm + GA + (wm * 32) * 132 + k0, 132);
            ldA(a1, sm + GA + (wm * 32 + 16) * 132 + k0, 132);
            #pragma unroll
            for (int t = 0; t < 4; ++t) {
                unsigned bb[2];
                ldB(bb, sm + GB + (wn * 32 + t * 8) * 132 + k0, 132);
                mma8(acc[0][t], a0[0], a0[1], a0[2], a0[3], bb[0], bb[1]);
                mma8(acc[1][t], a1[0], a1[1], a1[2], a1[3], bb[0], bb[1]);
            }
        }

        #pragma unroll
        for (int hf = 0; hf < 2; ++hf)
            #pragma unroll
            for (int t = 0; t < 4; ++t) {
                int col = nt * 64 + wn * 32 + t * 8 + 2 * ac;
                float sc = (qscale && col < 128) ? SCALE : 1.f;
                float b0v = __ldg(bias + col);
                float b1v = __ldg(bias + col + 1);
                long row = mt * 128 + wm * 32 + hf * 16 + ar;
                C[row * ldc + col]            = (acc[hf][t][0] + b0v) * sc;
                C[row * ldc + col + 1]        = (acc[hf][t][1] + b1v) * sc;
                C[(row + 8) * ldc + col]      = (acc[hf][t][2] + b0v) * sc;
                C[(row + 8) * ldc + col + 1]  = (acc[hf][t][3] + b1v) * sc;
            }

        if (pf) {
            __syncthreads();
            #pragma unroll
            for (int i = 0; i < 8; ++i) {
                int j = tid + i * 256;
                int r = j >> 5, c4 = j & 31;
                *(float4*)(sm + GB + r * 132 + c4 * 4) = f2tf4(breg[i]);
            }
            __syncthreads();
        }
    }
}

// ---------------- K2: attention per (window, head) ----------------
// 128 thr / 4 warps; warp wm owns rows [16*wm, 16*wm+16).
// Softmax + P all in registers (fragment domain); no score smem buffer.
// smem 28672 B -> 6 CTAs/SM (reg-limited).
constexpr int QS3 = 0;                   // Q 64 x 36
constexpr int KS3 = QS3 + 64 * 36;       // K 64 x 36
constexpr int VS3 = KS3 + 64 * 36;       // V 64 x 40 (conflict-free PV loads)
constexpr int ATTN_SMEM = (VS3 + 64 * 40) * 4;   // 28672 B

__global__ __launch_bounds__(128, 6)
void attn_kernel() {
    extern __shared__ float sm[];
    const int tid = threadIdx.x, lane = tid & 31, wm = tid >> 5;
    const int ar = lane >> 2, ac = lane & 3;
    const int win = blockIdx.x, h = blockIdx.y;
    const long tok0 = (long)win * NTOK;

    // zero V pad rows (49..63): P cols >=49 are exact 0, but 0*garbage-NaN would poison PV
    {
        const float4 z = make_float4(0.f, 0.f, 0.f, 0.f);
        for (int i = tid; i < 15 * 8; i += 128) {
            int r = 49 + (i >> 3), c4 = i & 7;
            *(float4*)(sm + VS3 + r * 40 + c4 * 4) = z;
        }
    }
    // stage q,k,v (49 rows x 32 cols each) as tf32
    {
        const float* qb = g_qkv + tok0 * 384 + h * 32;
        const float* kb = qb + 128;
        const float* vb = qb + 256;
        for (int i = tid; i < NTOK * 8; i += 128) {
            int r = i >> 3, c4 = (i & 7) * 4;
            long off = (long)r * 384 + c4;
            *(float4*)(sm + QS3 + r * 36 + c4) = f2tf4(__ldg((const float4*)(qb + off)));
            *(float4*)(sm + KS3 + r * 36 + c4) = f2tf4(__ldg((const float4*)(kb + off)));
            *(float4*)(sm + VS3 + r * 40 + c4) = f2tf4(__ldg((const float4*)(vb + off)));
        }
    }
    __syncthreads();

    // ---- scores S = Q_h @ K_h^T (64x64, K=32); warp tile 16x64, kept in fragments ----
    float sacc[8][4];
    #pragma unroll
    for (int t = 0; t < 8; ++t)
        #pragma unroll
        for (int j = 0; j < 4; ++j) sacc[t][j] = 0.f;

    #pragma unroll
    for (int kk = 0; kk < 4; ++kk) {
        int k0 = kk * 8;
        unsigned a[4];
        ldA(a, sm + QS3 + (wm * 16) * 36 + k0, 36);
        #pragma unroll
        for (int t = 0; t < 8; ++t) {
            unsigned bb[2];
            ldB(bb, sm + KS3 + (t * 8) * 36 + k0, 36);
            mma8(sacc[t], a[0], a[1], a[2], a[3], bb[0], bb[1]);
        }
    }

    // ---- softmax in fragment domain ----
    // C-fragment: sacc[t][0]=(r0, m0) [1]=(r0, m0+1) [2]=(r0+8, m0) [3]=(r0+8, m0+1),
    // r0 = wm*16+ar, m0 = t*8+2*ac. No max-subtraction (O(1)-scale scores).
    const int r0 = wm * 16 + ar, r1 = r0 + 8;
    const bool r0ok = r0 < NTOK, r1ok = r1 < NTOK;
    const float* bmh = g_bm + (size_t)((win & 63) * 4 + h) * 2401;

    float psum0 = 0.f, psum1 = 0.f;
    unsigned up[8][4];
    #pragma unroll
    for (int t = 0; t < 8; ++t) {
        int m0 = t * 8 + 2 * ac;
        bool c0 = m0 < NTOK, c1 = (m0 + 1) < NTOK;
        float b00 = (r0ok && c0) ? __ldg(bmh + r0 * 49 + m0)     : 0.f;
        float b01 = (r0ok && c1) ? __ldg(bmh + r0 * 49 + m0 + 1) : 0.f;
        float b10 = (r1ok && c0) ? __ldg(bmh + r1 * 49 + m0)     : 0.f;
        float b11 = (r1ok && c1) ? __ldg(bmh + r1 * 49 + m0 + 1) : 0.f;
        float e0 = (r0ok && c0) ? __expf(sacc[t][0] + b00) : 0.f;
        float e1 = (r0ok && c1) ? __expf(sacc[t][1] + b01) : 0.f;
        float e2 = (r1ok && c0) ? __expf(sacc[t][2] + b10) : 0.f;
        float e3 = (r1ok && c1) ? __expf(sacc[t][3] + b11) : 0.f;
        psum0 += e0 + e1;
        psum1 += e2 + e3;
        sacc[t][0] = e0; sacc[t][1] = e1; sacc[t][2] = e2; sacc[t][3] = e3;
    }
    // reduce across the 4 ac-lanes sharing each row (lane = ar*4 + ac)
    psum0 += __shfl_xor_sync(0xffffffffu, psum0, 1);
    psum0 += __shfl_xor_sync(0xffffffffu, psum0, 2);
    psum1 += __shfl_xor_sync(0xffffffffu, psum1, 1);
    psum1 += __shfl_xor_sync(0xffffffffu, psum1, 2);
    float inv0 = r0ok ? __fdividef(1.f, psum0) : 0.f;
    float inv1 = r1ok ? __fdividef(1.f, psum1) : 0.f;
    #pragma unroll
    for (int t = 0; t < 8; ++t) {
        up[t][0] = f2tf(sacc[t][0] * inv0);
        up[t][1] = f2tf(sacc[t][1] * inv0);
        up[t][2] = f2tf(sacc[t][2] * inv1);
        up[t][3] = f2tf(sacc[t][3] * inv1);
    }

    // ---- ctx = P @ V_h (64x32, K=64): shuffle-transpose C-frag -> A-frag per k-tile ----
    // A-frag needs a0=P[r0][kk*8+ac], a1=P[r1][same], a2/a3 at col+4.
    // P[.][kk*8+c] lives at lane (ar, c>>1), element c&1.
    float cacc[4][4];
    #pragma unroll
    for (int u = 0; u < 4; ++u)
        #pragma unroll
        for (int j = 0; j < 4; ++j) cacc[u][j] = 0.f;

    const int sl0 = (lane & 28) | (ac >> 1);
    const bool odd = ac & 1;
    #pragma unroll
    for (int kk = 0; kk < 8; ++kk) {
        unsigned q0 = __shfl_sync(0xffffffffu, up[kk][0], sl0);
        unsigned q1 = __shfl_sync(0xffffffffu, up[kk][1], sl0);
        unsigned q2 = __shfl_sync(0xffffffffu, up[kk][2], sl0);
        unsigned q3 = __shfl_sync(0xffffffffu, up[kk][3], sl0);
        unsigned s0 = __shfl_sync(0xffffffffu, up[kk][0], sl0 + 2);
        unsigned s1 = __shfl_sync(0xffffffffu, up[kk][1], sl0 + 2);
        unsigned s2 = __shfl_sync(0xffffffffu, up[kk][2], sl0 + 2);
        unsigned s3 = __shfl_sync(0xffffffffu, up[kk][3], sl0 + 2);
        unsigned a0 = odd ? q1 : q0;
        unsigned a1 = odd ? q3 : q2;
        unsigned a2 = odd ? s1 : s0;
        unsigned a3 = odd ? s3 : s2;
        #pragma unroll
        for (int u = 0; u < 4; ++u) {
            unsigned b0 = ldsm(sm + VS3 + (kk * 8 + ac) * 40 + u * 8 + ar);
            unsigned b1 = ldsm(sm + VS3 + (kk * 8 + 4 + ac) * 40 + u * 8 + ar);
            mma8(cacc[u], a0, a1, a2, a3, b0, b1);
        }
    }
    #pragma unroll
    for (int u = 0; u < 4; ++u) {
        int col = h * 32 + u * 8 + 2 * ac;
        if (r0ok)
            *(float2*)(g_ctx + (tok0 + r0) * 128 + col) =
                make_float2(cacc[u][0], cacc[u][1]);
        if (r1ok)
            *(float2*)(g_ctx + (tok0 + r1) * 128 + col) =
                make_float2(cacc[u][2], cacc[u][3]);
    }
}

// ---------------- launch ----------------
extern "C" void kernel_launch(void* const* d_in, const int* in_sizes, int n_in,
                              void* d_out, int out_size) {
    const float* x      = (const float*)d_in[0];
    const float* mask   = (const float*)d_in[1];
    const float* qkv_w  = (const float*)d_in[2];
    const float* qkv_b  = (const float*)d_in[3];
    const float* proj_w = (const float*)d_in[4];
    const float* proj_b = (const float*)d_in[5];
    const float* tbl    = (const float*)d_in[6];
    const int*   idx    = (const int*)d_in[7];

    cudaFuncSetAttribute(gemm_tf32_kernel,
                         cudaFuncAttributeMaxDynamicSharedMemorySize, GEMM_SMEM);
    cudaFuncSetAttribute(attn_kernel,
                         cudaFuncAttributeMaxDynamicSharedMemorySize, ATTN_SMEM);

    float* qkv_s; cudaGetSymbolAddress((void**)&qkv_s, g_qkv);
    float* ctx_s; cudaGetSymbolAddress((void**)&ctx_s, g_ctx);

    // K0: fused bias+mask
    biasfuse_kernel<<<2401, 256>>>(tbl, idx, mask);

    // K1: qkv GEMM (M=200704, N=384): A resident, 6 weight chunks streamed
    gemm_tf32_kernel<<<1568, 256, GEMM_SMEM>>>(x, qkv_w, qkv_b, qkv_s, 384, 6, 1);

    // K2: attention, one (window, head) per CTA
    {
        dim3 grid(4096, 4);
        attn_kernel<<<grid, 128, ATTN_SMEM>>>();
    }

    // K3: proj GEMM (M=200704, N=128): 2 weight chunks
    gemm_tf32_kernel<<<1568, 256, GEMM_SMEM>>>(ctx_s, proj_w, proj_b,
                                               (float*)d_out, 128, 2, 0);
}

// round 11
// speedup vs baseline: 2.3027x; 1.0080x over previous
#include <cuda_runtime.h>

// Swin window attention, 4-kernel split:
//  K0: fuse rel-pos bias + shift mask into g_bm[64][4][49][49]
//  K1: qkv GEMM  (M=200704, N=384, K=128) + bias, q pre-scaled -> g_qkv
//  K2: per-(window, head) attention -> g_ctx  (register softmax, normalize-after-PV)
//  K3: proj GEMM (M=200704, N=128, K=128) + bias -> out
// All GEMMs: mma.sync.m16n8k8 tf32, fragments via ldmatrix.

constexpr int NTOK = 49;
constexpr int NHD  = 4;
constexpr float SCALE = 0.17677669529663687f; // 32^-0.5
constexpr long long TOK = 200704ll;           // 4096 * 49

__device__ float g_qkv[TOK * 384];            // qkv activations (f32)
__device__ float g_ctx[TOK * 128];            // attention context (f32)
__device__ float g_bm[64 * 4 * 49 * 49 + 64]; // fused bias+mask (padded)

// ---------------- helpers ----------------
__device__ __forceinline__ unsigned f2tf(float x) {
    unsigned r;
    asm("cvt.rna.tf32.f32 %0, %1;" : "=r"(r) : "f"(x));
    return r;
}
__device__ __forceinline__ float4 f2tf4(float4 v) {
    float4 t;
    t.x = __uint_as_float(f2tf(v.x));
    t.y = __uint_as_float(f2tf(v.y));
    t.z = __uint_as_float(f2tf(v.z));
    t.w = __uint_as_float(f2tf(v.w));
    return t;
}
__device__ __forceinline__ void mma8(float c[4],
                                     unsigned a0, unsigned a1, unsigned a2, unsigned a3,
                                     unsigned b0, unsigned b1) {
    asm volatile(
        "mma.sync.aligned.m16n8k8.row.col.f32.tf32.tf32.f32 "
        "{%0,%1,%2,%3},{%4,%5,%6,%7},{%8,%9},{%0,%1,%2,%3};"
        : "+f"(c[0]), "+f"(c[1]), "+f"(c[2]), "+f"(c[3])
        : "r"(a0), "r"(a1), "r"(a2), "r"(a3), "r"(b0), "r"(b1));
}
__device__ __forceinline__ unsigned sptr(const float* p) {
    return (unsigned)__cvta_generic_to_shared(p);
}
__device__ __forceinline__ void ldA(unsigned r[4], const float* base, int L) {
    int lane = threadIdx.x & 31;
    const float* p = base + ((lane & 7) + ((lane & 8) ? 8 : 0)) * L + ((lane & 16) ? 4 : 0);
    unsigned a = sptr(p);
    asm volatile("ldmatrix.sync.aligned.m8n8.x4.shared.b16 {%0,%1,%2,%3}, [%4];"
                 : "=r"(r[0]), "=r"(r[1]), "=r"(r[2]), "=r"(r[3]) : "r"(a));
}
__device__ __forceinline__ void ldB(unsigned r[2], const float* base, int L) {
    int lane = threadIdx.x & 31;
    const float* p = base + (lane & 7) * L + ((lane & 8) ? 4 : 0);
    unsigned a = sptr(p);
    asm volatile("ldmatrix.sync.aligned.m8n8.x2.shared.b16 {%0,%1}, [%2];"
                 : "=r"(r[0]), "=r"(r[1]) : "r"(a));
}
__device__ __forceinline__ unsigned ldsm(const float* p) { return __float_as_uint(*p); }

// ---------------- K0: fused bias+mask table ----------------
__global__ void biasfuse_kernel(const float* __restrict__ tbl,
                                const int*   __restrict__ idx,
                                const float* __restrict__ mask) {
    long i = (long)blockIdx.x * 256 + threadIdx.x;   // 64*4*49*49 = 614656 exactly
    int m = (int)(i % 49);
    long r = i / 49;
    int n = (int)(r % 49); r /= 49;
    int h = (int)(r % 4);
    int wn = (int)(r / 4);
    g_bm[i] = __ldg(tbl + __ldg(idx + n * 49 + m) * NHD + h)
            + __ldg(mask + wn * 2401 + n * 49 + m);
}

// ---------------- K1/K3: GEMM  C[M,N] = A[M,128] @ W[N,128]^T + bias ----------------
// A tile (128x128) resident; W streamed in 64-col chunks with register prefetch.
constexpr int GA = 0;                 // A tile 128 x 132
constexpr int GB = 128 * 132;         // B chunk 64 x 132
constexpr int GEMM_SMEM = (128 * 132 + 64 * 132) * 4;   // 101376 B

__global__ __launch_bounds__(256, 2)
void gemm_tf32_kernel(const float* __restrict__ A,
                      const float* __restrict__ W,
                      const float* __restrict__ bias,
                      float* __restrict__ C,
                      int ldc, int n_chunks, int qscale) {
    extern __shared__ float sm[];
    const int tid = threadIdx.x, lane = tid & 31, w = tid >> 5;
    const int wm = w & 3, wn = w >> 2;
    const int ar = lane >> 2, ac = lane & 3;
    const long mt = blockIdx.x;

    // stage A (128x128 = 4096 float4 -> tf32, STS.128), once
    {
        const float4* ag = (const float4*)(A + mt * 128 * 128);
        #pragma unroll
        for (int i = 0; i < 16; ++i) {
            int j = tid + i * 256;
            int r = j >> 5, c4 = j & 31;
            *(float4*)(sm + GA + r * 132 + c4 * 4) = f2tf4(__ldg(ag + j));
        }
    }
    // stage B chunk 0 (64x128 = 2048 float4)
    {
        const float4* wg = (const float4*)W;
        #pragma unroll
        for (int i = 0; i < 8; ++i) {
            int j = tid + i * 256;
            int r = j >> 5, c4 = j & 31;
            *(float4*)(sm + GB + r * 132 + c4 * 4) = f2tf4(__ldg(wg + j));
        }
    }
    __syncthreads();

    for (int nt = 0; nt < n_chunks; ++nt) {
        float4 breg[8];
        const bool pf = (nt + 1 < n_chunks);
        if (pf) {
            const float4* wg = (const float4*)(W + (long)(nt + 1) * 64 * 128);
            #pragma unroll
            for (int i = 0; i < 8; ++i) breg[i] = __ldg(wg + tid + i * 256);
        }

        float acc[2][4][4];
        #pragma unroll
        for (int hf = 0; hf < 2; ++hf)
            #pragma unroll
            for (int t = 0; t < 4; ++t)
                #pragma unroll
                for (int j = 0; j < 4; ++j) acc[hf][t][j] = 0.f;

        #pragma unroll 4
        for (int k0 = 0; k0 < 128; k0 += 8) {
            unsigned a0[4], a1[4];
            ldA(a0, sm + GA + (wm * 32) * 132 + k0, 132);
            ldA(a1, sm + GA + (wm * 32 + 16) * 132 + k0, 132);
            #pragma unroll
            for (int t = 0; t < 4; ++t) {
                unsigned bb[2];
                ldB(bb, sm + GB + (wn * 32 + t * 8) * 132 + k0, 132);
                mma8(acc[0][t], a0[0], a0[1], a0[2], a0[3], bb[0], bb[1]);
                mma8(acc[1][t], a1[0], a1[1], a1[2], a1[3], bb[0], bb[1]);
            }
        }

        #pragma unroll
        for (int hf = 0; hf < 2; ++hf)
            #pragma unroll
            for (int t = 0; t < 4; ++t) {
                int col = nt * 64 + wn * 32 + t * 8 + 2 * ac;
                float sc = (qscale && col < 128) ? SCALE : 1.f;
                float b0v = __ldg(bias + col);
                float b1v = __ldg(bias + col + 1);
                long row = mt * 128 + wm * 32 + hf * 16 + ar;
                C[row * ldc + col]            = (acc[hf][t][0] + b0v) * sc;
                C[row * ldc + col + 1]        = (acc[hf][t][1] + b1v) * sc;
                C[(row + 8) * ldc + col]      = (acc[hf][t][2] + b0v) * sc;
                C[(row + 8) * ldc + col + 1]  = (acc[hf][t][3] + b1v) * sc;
            }

        if (pf) {
            __syncthreads();
            #pragma unroll
            for (int i = 0; i < 8; ++i) {
                int j = tid + i * 256;
                int r = j >> 5, c4 = j & 31;
                *(float4*)(sm + GB + r * 132 + c4 * 4) = f2tf4(breg[i]);
            }
            __syncthreads();
        }
    }
}

// ---------------- K2: attention per (window, head) ----------------
// 128 thr / 4 warps; warp wm owns rows [16*wm, 16*wm+16).
// Fragment-domain softmax; PV on UNNORMALIZED e, row-scale by 1/sum in epilogue
// (row scaling commutes with the GEMM). Peak live regs ~50 -> no spills at the
// 85-reg cap imposed by __launch_bounds__(128, 6).
constexpr int QS3 = 0;                   // Q 64 x 36
constexpr int KS3 = QS3 + 64 * 36;       // K 64 x 36
constexpr int VS3 = KS3 + 64 * 36;       // V 64 x 40 (conflict-free PV loads)
constexpr int ATTN_SMEM = (VS3 + 64 * 40) * 4;   // 28672 B -> 6 CTAs/SM

__global__ __launch_bounds__(128, 6)
void attn_kernel() {
    extern __shared__ float sm[];
    const int tid = threadIdx.x, lane = tid & 31, wm = tid >> 5;
    const int ar = lane >> 2, ac = lane & 3;
    const int win = blockIdx.x, h = blockIdx.y;
    const long tok0 = (long)win * NTOK;

    // zero V pad rows (49..63): P cols >=49 are exact 0, but 0*garbage-NaN would poison PV
    {
        const float4 z = make_float4(0.f, 0.f, 0.f, 0.f);
        for (int i = tid; i < 15 * 8; i += 128) {
            int r = 49 + (i >> 3), c4 = i & 7;
            *(float4*)(sm + VS3 + r * 40 + c4 * 4) = z;
        }
    }
    // stage q,k,v (49 rows x 32 cols each) as tf32
    {
        const float* qb = g_qkv + tok0 * 384 + h * 32;
        const float* kb = qb + 128;
        const float* vb = qb + 256;
        for (int i = tid; i < NTOK * 8; i += 128) {
            int r = i >> 3, c4 = (i & 7) * 4;
            long off = (long)r * 384 + c4;
            *(float4*)(sm + QS3 + r * 36 + c4) = f2tf4(__ldg((const float4*)(qb + off)));
            *(float4*)(sm + KS3 + r * 36 + c4) = f2tf4(__ldg((const float4*)(kb + off)));
            *(float4*)(sm + VS3 + r * 40 + c4) = f2tf4(__ldg((const float4*)(vb + off)));
        }
    }
    __syncthreads();

    // ---- scores S = Q_h @ K_h^T (64x64, K=32); warp tile 16x64, kept in fragments ----
    float sacc[8][4];
    #pragma unroll
    for (int t = 0; t < 8; ++t)
        #pragma unroll
        for (int j = 0; j < 4; ++j) sacc[t][j] = 0.f;

    #pragma unroll
    for (int kk = 0; kk < 4; ++kk) {
        int k0 = kk * 8;
        unsigned a[4];
        ldA(a, sm + QS3 + (wm * 16) * 36 + k0, 36);
        #pragma unroll
        for (int t = 0; t < 8; ++t) {
            unsigned bb[2];
            ldB(bb, sm + KS3 + (t * 8) * 36 + k0, 36);
            mma8(sacc[t], a[0], a[1], a[2], a[3], bb[0], bb[1]);
        }
    }

    // ---- softmax numerator in fragment domain ----
    // C-fragment: sacc[t][0]=(r0, m0) [1]=(r0, m0+1) [2]=(r0+8, m0) [3]=(r0+8, m0+1),
    // r0 = wm*16+ar, m0 = t*8+2*ac. No max-subtraction (O(1)-scale scores).
    const int r0 = wm * 16 + ar, r1 = r0 + 8;
    const bool r0ok = r0 < NTOK, r1ok = r1 < NTOK;
    const float* bmh = g_bm + (size_t)((win & 63) * 4 + h) * 2401;

    float psum0 = 0.f, psum1 = 0.f;
    #pragma unroll
    for (int t = 0; t < 8; ++t) {
        int m0 = t * 8 + 2 * ac;
        bool c0 = m0 < NTOK, c1 = (m0 + 1) < NTOK;
        float b00 = (r0ok && c0) ? __ldg(bmh + r0 * 49 + m0)     : 0.f;
        float b01 = (r0ok && c1) ? __ldg(bmh + r0 * 49 + m0 + 1) : 0.f;
        float b10 = (r1ok && c0) ? __ldg(bmh + r1 * 49 + m0)     : 0.f;
        float b11 = (r1ok && c1) ? __ldg(bmh + r1 * 49 + m0 + 1) : 0.f;
        float e0 = (r0ok && c0) ? __expf(sacc[t][0] + b00) : 0.f;
        float e1 = (r0ok && c1) ? __expf(sacc[t][1] + b01) : 0.f;
        float e2 = (r1ok && c0) ? __expf(sacc[t][2] + b10) : 0.f;
        float e3 = (r1ok && c1) ? __expf(sacc[t][3] + b11) : 0.f;
        psum0 += e0 + e1;
        psum1 += e2 + e3;
        // tf32-round unnormalized e in place (normalization deferred to epilogue)
        sacc[t][0] = __uint_as_float(f2tf(e0));
        sacc[t][1] = __uint_as_float(f2tf(e1));
        sacc[t][2] = __uint_as_float(f2tf(e2));
        sacc[t][3] = __uint_as_float(f2tf(e3));
    }
    // row sums across the 4 ac-lanes sharing each row (lane = ar*4 + ac)
    psum0 += __shfl_xor_sync(0xffffffffu, psum0, 1);
    psum0 += __shfl_xor_sync(0xffffffffu, psum0, 2);
    psum1 += __shfl_xor_sync(0xffffffffu, psum1, 1);
    psum1 += __shfl_xor_sync(0xffffffffu, psum1, 2);
    const float inv0 = r0ok ? __fdividef(1.f, psum0) : 0.f;
    const float inv1 = r1ok ? __fdividef(1.f, psum1) : 0.f;

    // ---- ctx = (E @ V_h) * inv (64x32, K=64): shuffle-transpose C-frag -> A-frag ----
    // A-frag needs a0=E[r0][kk*8+ac], a1=E[r1][same], a2/a3 at col+4.
    // E[.][kk*8+c] lives at lane (ar, c>>1), element c&1.
    float cacc[4][4];
    #pragma unroll
    for (int u = 0; u < 4; ++u)
        #pragma unroll
        for (int j = 0; j < 4; ++j) cacc[u][j] = 0.f;

    const int sl0 = (lane & 28) | (ac >> 1);
    const bool odd = ac & 1;
    #pragma unroll
    for (int kk = 0; kk < 8; ++kk) {
        float q0 = __shfl_sync(0xffffffffu, sacc[kk][0], sl0);
        float q1 = __shfl_sync(0xffffffffu, sacc[kk][1], sl0);
        float q2 = __shfl_sync(0xffffffffu, sacc[kk][2], sl0);
        float q3 = __shfl_sync(0xffffffffu, sacc[kk][3], sl0);
        float s0 = __shfl_sync(0xffffffffu, sacc[kk][0], sl0 + 2);
        float s1 = __shfl_sync(0xffffffffu, sacc[kk][1], sl0 + 2);
        float s2 = __shfl_sync(0xffffffffu, sacc[kk][2], sl0 + 2);
        float s3 = __shfl_sync(0xffffffffu, sacc[kk][3], sl0 + 2);
        unsigned a0 = __float_as_uint(odd ? q1 : q0);
        unsigned a1 = __float_as_uint(odd ? q3 : q2);
        unsigned a2 = __float_as_uint(odd ? s1 : s0);
        unsigned a3 = __float_as_uint(odd ? s3 : s2);
        #pragma unroll
        for (int u = 0; u < 4; ++u) {
            unsigned b0 = ldsm(sm + VS3 + (kk * 8 + ac) * 40 + u * 8 + ar);
            unsigned b1 = ldsm(sm + VS3 + (kk * 8 + 4 + ac) * 40 + u * 8 + ar);
            mma8(cacc[u], a0, a1, a2, a3, b0, b1);
        }
    }
    #pragma unroll
    for (int u = 0; u < 4; ++u) {
        int col = h * 32 + u * 8 + 2 * ac;
        if (r0ok)
            *(float2*)(g_ctx + (tok0 + r0) * 128 + col) =
                make_float2(cacc[u][0] * inv0, cacc[u][1] * inv0);
        if (r1ok)
            *(float2*)(g_ctx + (tok0 + r1) * 128 + col) =
                make_float2(cacc[u][2] * inv1, cacc[u][3] * inv1);
    }
}

// ---------------- launch ----------------
extern "C" void kernel_launch(void* const* d_in, const int* in_sizes, int n_in,
                              void* d_out, int out_size) {
    const float* x      = (const float*)d_in[0];
    const float* mask   = (const float*)d_in[1];
    const float* qkv_w  = (const float*)d_in[2];
    const float* qkv_b  = (const float*)d_in[3];
    const float* proj_w = (const float*)d_in[4];
    const float* proj_b = (const float*)d_in[5];
    const float* tbl    = (const float*)d_in[6];
    const int*   idx    = (const int*)d_in[7];

    cudaFuncSetAttribute(gemm_tf32_kernel,
                         cudaFuncAttributeMaxDynamicSharedMemorySize, GEMM_SMEM);
    cudaFuncSetAttribute(attn_kernel,
                         cudaFuncAttributeMaxDynamicSharedMemorySize, ATTN_SMEM);

    float* qkv_s; cudaGetSymbolAddress((void**)&qkv_s, g_qkv);
    float* ctx_s; cudaGetSymbolAddress((void**)&ctx_s, g_ctx);

    // K0: fused bias+mask
    biasfuse_kernel<<<2401, 256>>>(tbl, idx, mask);

    // K1: qkv GEMM (M=200704, N=384): A resident, 6 weight chunks streamed
    gemm_tf32_kernel<<<1568, 256, GEMM_SMEM>>>(x, qkv_w, qkv_b, qkv_s, 384, 6, 1);

    // K2: attention, one (window, head) per CTA
    {
        dim3 grid(4096, 4);
        attn_kernel<<<grid, 128, ATTN_SMEM>>>();
    }

    // K3: proj GEMM (M=200704, N=128): 2 weight chunks
    gemm_tf32_kernel<<<1568, 256, GEMM_SMEM>>>(ctx_s, proj_w, proj_b,
                                               (float*)d_out, 128, 2, 0);
}